// round 2
// baseline (speedup 1.0000x reference)
#include <cuda_runtime.h>
#include <cstdint>

#define BSZ 4
#define NSEQ 2048
#define DMODEL 512
#define NHEAD 8
#define DK 64
#define BH (BSZ * NHEAD)          // 32
#define M_ROWS (BSZ * NSEQ)      // 8192
#define THREE_D (3 * DMODEL)     // 1536
#define MASK_ELEMS ((size_t)BSZ * NSEQ * NSEQ)   // 16,777,216

// Scratch
__device__ float g_qkv[(size_t)3 * BH * NSEQ * DK];     // ~50 MB
__device__ float g_att[(size_t)BSZ * NSEQ * DMODEL];    // ~17 MB
__device__ unsigned char g_mask8[MASK_ELEMS];           // 16 MB
__device__ int g_mask_mode;                             // 0=u8, 1=i32, 2=f32

// ---------------------------------------------------------------------------
// Kernel 0a: detect mask dtype from raw words.
//   uint8 bools  -> words like 0x00010101 (value >1, != 0x3F800000)
//   int32 bools  -> all words are 0 or 1
//   float32 bools-> words 0 or 0x3F800000
// ---------------------------------------------------------------------------
__global__ void mask_detect_kernel(const unsigned int* __restrict__ m)
{
    __shared__ int sawBig, sawFloatOne;
    if (threadIdx.x == 0) { sawBig = 0; sawFloatOne = 0; }
    __syncthreads();
    for (int i = threadIdx.x; i < 16384; i += blockDim.x) {
        unsigned int w = m[i];
        if (w == 0x3F800000u) atomicOr(&sawFloatOne, 1);
        else if (w > 1u) atomicOr(&sawBig, 1);
    }
    __syncthreads();
    if (threadIdx.x == 0)
        g_mask_mode = sawFloatOne ? 2 : (sawBig ? 0 : 1);
}

// Kernel 0b: normalize mask to uint8 in g_mask8
__global__ __launch_bounds__(256) void mask_convert_kernel(const void* __restrict__ m)
{
    const size_t i = (size_t)blockIdx.x * blockDim.x + threadIdx.x;
    if (i >= MASK_ELEMS) return;
    const int mode = g_mask_mode;
    unsigned char v;
    if (mode == 0)      v = ((const unsigned char*)m)[i] != 0;
    else if (mode == 1) v = ((const int*)m)[i] != 0;
    else                v = ((const float*)m)[i] != 0.0f;
    g_mask8[i] = v;
}

// ---------------------------------------------------------------------------
// Kernel 1: QKV projection. C[8192,1536] = X[8192,512] @ Wqkv[512,1536],
// epilogue scatters into g_qkv[[3][b*H+h][n][dk]].
// ---------------------------------------------------------------------------
__global__ __launch_bounds__(256) void qkv_gemm_kernel(
    const float* __restrict__ X, const float* __restrict__ W)
{
    __shared__ float As[16][64];   // [k][row]
    __shared__ float Bs[16][64];   // [k][col]

    const int tid = threadIdx.x;
    const int tx = tid & 15, ty = tid >> 4;
    const int n0 = blockIdx.x << 6;
    const int m0 = blockIdx.y << 6;

    float acc[4][4] = {};

    const int ar = tid >> 2, ak = (tid & 3) << 2;
    const int bk = tid >> 4, bc = (tid & 15) << 2;
    const float* Xp = X + (size_t)(m0 + ar) * DMODEL + ak;
    const float* Wp = W + (size_t)bk * THREE_D + n0 + bc;

    for (int k0 = 0; k0 < DMODEL; k0 += 16) {
        float4 av = *(const float4*)(Xp + k0);
        As[ak + 0][ar] = av.x; As[ak + 1][ar] = av.y;
        As[ak + 2][ar] = av.z; As[ak + 3][ar] = av.w;
        *(float4*)&Bs[bk][bc] = *(const float4*)(Wp + (size_t)k0 * THREE_D);
        __syncthreads();
#pragma unroll
        for (int kk = 0; kk < 16; kk++) {
            float4 a4 = *(const float4*)&As[kk][ty << 2];
            float4 b4 = *(const float4*)&Bs[kk][tx << 2];
            float a[4] = {a4.x, a4.y, a4.z, a4.w};
            float b[4] = {b4.x, b4.y, b4.z, b4.w};
#pragma unroll
            for (int i = 0; i < 4; i++)
#pragma unroll
                for (int j = 0; j < 4; j++) acc[i][j] += a[i] * b[j];
        }
        __syncthreads();
    }

#pragma unroll
    for (int i = 0; i < 4; i++) {
        const int m = m0 + (ty << 2) + i;
        const int b = m >> 11;
        const int n = m & (NSEQ - 1);
#pragma unroll
        for (int j = 0; j < 4; j++) {
            const int c = n0 + (tx << 2) + j;
            const int which = c >> 9;
            const int dd = c & 511;
            const int h = dd >> 6;
            const int dk = dd & 63;
            g_qkv[((((size_t)which * BSZ + b) * NHEAD + h) * NSEQ + n) * DK + dk] =
                acc[i][j];
        }
    }
}

// ---------------------------------------------------------------------------
// Kernel 2: streaming masked attention (flash-style, fp32).
// ---------------------------------------------------------------------------
__global__ __launch_bounds__(256) void attn_kernel()
{
    extern __shared__ float sm[];
    float* Qt = sm;                 // [dk][row]
    float* Ks = sm + 4096;          // [dk][key]
    float* Vs = sm + 8192;          // [key][dk]
    float* Ps = sm + 12288;         // [key][row]

    const int tid = threadIdx.x;
    const int tx = tid & 15, ty = tid >> 4;
    const int qrow0 = blockIdx.x << 6;
    const int bh = blockIdx.y;
    const int b = bh >> 3;
    const int h = bh & 7;

    const float* Qg = g_qkv + (size_t)bh * NSEQ * DK;
    const float* Kg = g_qkv + (size_t)(BH + bh) * NSEQ * DK;
    const float* Vg = g_qkv + (size_t)(2 * BH + bh) * NSEQ * DK;

    for (int e = tid; e < 1024; e += 256) {
        const int row = e >> 4;
        const int d4 = (e & 15) << 2;
        float4 v = *(const float4*)&Qg[(size_t)(qrow0 + row) * DK + d4];
        Qt[(d4 + 0) * 64 + row] = v.x; Qt[(d4 + 1) * 64 + row] = v.y;
        Qt[(d4 + 2) * 64 + row] = v.z; Qt[(d4 + 3) * 64 + row] = v.w;
    }

    float o[4][4] = {};
    float mrow[4], lrow[4];
#pragma unroll
    for (int i = 0; i < 4; i++) { mrow[i] = -1e30f; lrow[i] = 0.f; }

    const unsigned char* mbase =
        g_mask8 + ((size_t)b * NSEQ + qrow0 + (ty << 2)) * NSEQ + (tx << 2);

    __syncthreads();

    for (int kt = 0; kt < NSEQ / 64; kt++) {
        const int kcol0 = kt << 6;
        for (int e = tid; e < 1024; e += 256) {
            const int row = e >> 4;
            const int d4 = (e & 15) << 2;
            float4 kv = *(const float4*)&Kg[(size_t)(kcol0 + row) * DK + d4];
            Ks[(d4 + 0) * 64 + row] = kv.x; Ks[(d4 + 1) * 64 + row] = kv.y;
            Ks[(d4 + 2) * 64 + row] = kv.z; Ks[(d4 + 3) * 64 + row] = kv.w;
            *(float4*)&Vs[row * 64 + d4] =
                *(const float4*)&Vg[(size_t)(kcol0 + row) * DK + d4];
        }
        __syncthreads();

        float s[4][4] = {};
#pragma unroll 16
        for (int kk = 0; kk < 64; kk++) {
            float4 a4 = *(const float4*)&Qt[kk * 64 + (ty << 2)];
            float4 b4 = *(const float4*)&Ks[kk * 64 + (tx << 2)];
            float a[4] = {a4.x, a4.y, a4.z, a4.w};
            float bb[4] = {b4.x, b4.y, b4.z, b4.w};
#pragma unroll
            for (int i = 0; i < 4; i++)
#pragma unroll
                for (int j = 0; j < 4; j++) s[i][j] += a[i] * bb[j];
        }

#pragma unroll
        for (int i = 0; i < 4; i++) {
            uchar4 mk = *(const uchar4*)(mbase + (size_t)i * NSEQ + kcol0);
            float sv[4];
            sv[0] = mk.x ? s[i][0] * 0.125f : -1e30f;
            sv[1] = mk.y ? s[i][1] * 0.125f : -1e30f;
            sv[2] = mk.z ? s[i][2] * 0.125f : -1e30f;
            sv[3] = mk.w ? s[i][3] * 0.125f : -1e30f;
            float rm = fmaxf(fmaxf(sv[0], sv[1]), fmaxf(sv[2], sv[3]));
            rm = fmaxf(rm, __shfl_xor_sync(0xffffffffu, rm, 1));
            rm = fmaxf(rm, __shfl_xor_sync(0xffffffffu, rm, 2));
            rm = fmaxf(rm, __shfl_xor_sync(0xffffffffu, rm, 4));
            rm = fmaxf(rm, __shfl_xor_sync(0xffffffffu, rm, 8));
            const float mnew = fmaxf(mrow[i], rm);
            const float alpha = __expf(mrow[i] - mnew);
            float p[4];
            p[0] = mk.x ? __expf(sv[0] - mnew) : 0.f;
            p[1] = mk.y ? __expf(sv[1] - mnew) : 0.f;
            p[2] = mk.z ? __expf(sv[2] - mnew) : 0.f;
            p[3] = mk.w ? __expf(sv[3] - mnew) : 0.f;
            float rs = p[0] + p[1] + p[2] + p[3];
            rs += __shfl_xor_sync(0xffffffffu, rs, 1);
            rs += __shfl_xor_sync(0xffffffffu, rs, 2);
            rs += __shfl_xor_sync(0xffffffffu, rs, 4);
            rs += __shfl_xor_sync(0xffffffffu, rs, 8);
            lrow[i] = lrow[i] * alpha + rs;
            mrow[i] = mnew;
#pragma unroll
            for (int j = 0; j < 4; j++) {
                o[i][j] *= alpha;
                Ps[((tx << 2) + j) * 64 + (ty << 2) + i] = p[j];
            }
        }
        __syncthreads();

#pragma unroll 16
        for (int kk = 0; kk < 64; kk++) {
            float4 a4 = *(const float4*)&Ps[kk * 64 + (ty << 2)];
            float4 b4 = *(const float4*)&Vs[kk * 64 + (tx << 2)];
            float a[4] = {a4.x, a4.y, a4.z, a4.w};
            float bb[4] = {b4.x, b4.y, b4.z, b4.w};
#pragma unroll
            for (int i = 0; i < 4; i++)
#pragma unroll
                for (int j = 0; j < 4; j++) o[i][j] += a[i] * bb[j];
        }
        __syncthreads();
    }

#pragma unroll
    for (int i = 0; i < 4; i++) {
        const float inv = 1.f / lrow[i];
        const int n = qrow0 + (ty << 2) + i;
        float* outp = g_att + ((size_t)b * NSEQ + n) * DMODEL + h * DK + (tx << 2);
        *(float4*)outp = make_float4(o[i][0] * inv, o[i][1] * inv,
                                     o[i][2] * inv, o[i][3] * inv);
    }
}

// ---------------------------------------------------------------------------
// Kernel 3: output projection + bias + LeakyReLU.
// ---------------------------------------------------------------------------
__global__ __launch_bounds__(256) void out_gemm_kernel(
    const float* __restrict__ W, const float* __restrict__ bias,
    float* __restrict__ out)
{
    __shared__ float As[16][64];
    __shared__ float Bs[16][64];

    const int tid = threadIdx.x;
    const int tx = tid & 15, ty = tid >> 4;
    const int n0 = blockIdx.x << 6;
    const int m0 = blockIdx.y << 6;

    float acc[4][4] = {};

    const int ar = tid >> 2, ak = (tid & 3) << 2;
    const int bk = tid >> 4, bc = (tid & 15) << 2;
    const float* Xp = g_att + (size_t)(m0 + ar) * DMODEL + ak;
    const float* Wp = W + (size_t)bk * DMODEL + n0 + bc;

    for (int k0 = 0; k0 < DMODEL; k0 += 16) {
        float4 av = *(const float4*)(Xp + k0);
        As[ak + 0][ar] = av.x; As[ak + 1][ar] = av.y;
        As[ak + 2][ar] = av.z; As[ak + 3][ar] = av.w;
        *(float4*)&Bs[bk][bc] = *(const float4*)(Wp + (size_t)k0 * DMODEL);
        __syncthreads();
#pragma unroll
        for (int kk = 0; kk < 16; kk++) {
            float4 a4 = *(const float4*)&As[kk][ty << 2];
            float4 b4 = *(const float4*)&Bs[kk][tx << 2];
            float a[4] = {a4.x, a4.y, a4.z, a4.w};
            float b[4] = {b4.x, b4.y, b4.z, b4.w};
#pragma unroll
            for (int i = 0; i < 4; i++)
#pragma unroll
                for (int j = 0; j < 4; j++) acc[i][j] += a[i] * b[j];
        }
        __syncthreads();
    }

#pragma unroll
    for (int i = 0; i < 4; i++) {
        const int m = m0 + (ty << 2) + i;
#pragma unroll
        for (int j = 0; j < 4; j++) {
            const int c = n0 + (tx << 2) + j;
            float v = acc[i][j] + bias[c];
            out[(size_t)m * DMODEL + c] = (v >= 0.f) ? v : 0.1f * v;
        }
    }
}

// ---------------------------------------------------------------------------
extern "C" void kernel_launch(void* const* d_in, const int* in_sizes, int n_in,
                              void* d_out, int out_size)
{
    // Identify inputs by element count (robust to metadata ordering).
    const float* x = nullptr;
    const void* mask = nullptr;
    const float* Wqkv = nullptr;
    const float* Wout = nullptr;
    const float* bout = nullptr;
    for (int i = 0; i < n_in; i++) {
        switch (in_sizes[i]) {
            case 4194304:  x    = (const float*)d_in[i]; break;  // 4*2048*512
            case 16777216: mask = d_in[i];               break;  // 4*2048*2048
            case 786432:   Wqkv = (const float*)d_in[i]; break;  // 512*1536
            case 262144:   Wout = (const float*)d_in[i]; break;  // 512*512
            case 512:      bout = (const float*)d_in[i]; break;  // 512
        }
    }
    float* out = (float*)d_out;

    cudaFuncSetAttribute(attn_kernel,
                         cudaFuncAttributeMaxDynamicSharedMemorySize, 65536);

    mask_detect_kernel<<<1, 256>>>((const unsigned int*)mask);
    mask_convert_kernel<<<(unsigned)((MASK_ELEMS + 255) / 256), 256>>>(mask);
    qkv_gemm_kernel<<<dim3(THREE_D / 64, M_ROWS / 64), 256>>>(x, Wqkv);
    attn_kernel<<<dim3(NSEQ / 64, BH), 256, 65536>>>();
    out_gemm_kernel<<<dim3(DMODEL / 64, M_ROWS / 64), 256>>>(Wout, bout, out);
}

// round 3
// speedup vs baseline: 1.8030x; 1.8030x over previous
#include <cuda_runtime.h>
#include <cstdint>

#define BSZ 4
#define NSEQ 2048
#define DMODEL 512
#define NHEAD 8
#define DK 64
#define BH (BSZ * NHEAD)          // 32
#define M_ROWS (BSZ * NSEQ)       // 8192
#define THREE_D (3 * DMODEL)      // 1536
#define MASK_ELEMS ((size_t)BSZ * NSEQ * NSEQ)   // 16,777,216

// Scratch
__device__ float g_qkv[(size_t)3 * BH * NSEQ * DK];     // ~50 MB
__device__ float g_att[(size_t)BSZ * NSEQ * DMODEL];    // ~17 MB
__device__ unsigned char g_mask8[MASK_ELEMS];           // 16 MB
__device__ int g_mask_mode;                             // 0=u8, 1=i32, 2=f32

// ---------------------------------------------------------------------------
// tf32 helpers
// ---------------------------------------------------------------------------
__device__ __forceinline__ unsigned int f2tf(float f) {
    unsigned int u;
    asm("cvt.rna.tf32.f32 %0, %1;" : "=r"(u) : "f"(f));
    return u;
}

__device__ __forceinline__ void mma_tf32(float* c, const unsigned int* a,
                                         unsigned int b0, unsigned int b1) {
    asm volatile(
        "mma.sync.aligned.m16n8k8.row.col.f32.tf32.tf32.f32 "
        "{%0,%1,%2,%3}, {%4,%5,%6,%7}, {%8,%9}, {%0,%1,%2,%3};"
        : "+f"(c[0]), "+f"(c[1]), "+f"(c[2]), "+f"(c[3])
        : "r"(a[0]), "r"(a[1]), "r"(a[2]), "r"(a[3]), "r"(b0), "r"(b1));
}

// ---------------------------------------------------------------------------
// Kernel 0a: detect mask dtype from raw words.
// ---------------------------------------------------------------------------
__global__ void mask_detect_kernel(const unsigned int* __restrict__ m)
{
    __shared__ int sawBig, sawFloatOne;
    if (threadIdx.x == 0) { sawBig = 0; sawFloatOne = 0; }
    __syncthreads();
    for (int i = threadIdx.x; i < 16384; i += blockDim.x) {
        unsigned int w = m[i];
        if (w == 0x3F800000u) atomicOr(&sawFloatOne, 1);
        else if (w > 1u) atomicOr(&sawBig, 1);
    }
    __syncthreads();
    if (threadIdx.x == 0)
        g_mask_mode = sawFloatOne ? 2 : (sawBig ? 0 : 1);
}

// Kernel 0b: normalize mask to uint8 in g_mask8
__global__ __launch_bounds__(256) void mask_convert_kernel(const void* __restrict__ m)
{
    const size_t i = (size_t)blockIdx.x * blockDim.x + threadIdx.x;
    if (i >= MASK_ELEMS) return;
    const int mode = g_mask_mode;
    unsigned char v;
    if (mode == 0)      v = ((const unsigned char*)m)[i] != 0;
    else if (mode == 1) v = ((const int*)m)[i] != 0;
    else                v = ((const float*)m)[i] != 0.0f;
    g_mask8[i] = v;
}

// ---------------------------------------------------------------------------
// Kernel 1: QKV projection (fp32 scalar), epilogue scatter to [3][bh][n][dk].
// ---------------------------------------------------------------------------
__global__ __launch_bounds__(256) void qkv_gemm_kernel(
    const float* __restrict__ X, const float* __restrict__ W)
{
    __shared__ float As[16][64];
    __shared__ float Bs[16][64];

    const int tid = threadIdx.x;
    const int tx = tid & 15, ty = tid >> 4;
    const int n0 = blockIdx.x << 6;
    const int m0 = blockIdx.y << 6;

    float acc[4][4] = {};

    const int ar = tid >> 2, ak = (tid & 3) << 2;
    const int bk = tid >> 4, bc = (tid & 15) << 2;
    const float* Xp = X + (size_t)(m0 + ar) * DMODEL + ak;
    const float* Wp = W + (size_t)bk * THREE_D + n0 + bc;

    for (int k0 = 0; k0 < DMODEL; k0 += 16) {
        float4 av = *(const float4*)(Xp + k0);
        As[ak + 0][ar] = av.x; As[ak + 1][ar] = av.y;
        As[ak + 2][ar] = av.z; As[ak + 3][ar] = av.w;
        *(float4*)&Bs[bk][bc] = *(const float4*)(Wp + (size_t)k0 * THREE_D);
        __syncthreads();
#pragma unroll
        for (int kk = 0; kk < 16; kk++) {
            float4 a4 = *(const float4*)&As[kk][ty << 2];
            float4 b4 = *(const float4*)&Bs[kk][tx << 2];
            float a[4] = {a4.x, a4.y, a4.z, a4.w};
            float b[4] = {b4.x, b4.y, b4.z, b4.w};
#pragma unroll
            for (int i = 0; i < 4; i++)
#pragma unroll
                for (int j = 0; j < 4; j++) acc[i][j] += a[i] * b[j];
        }
        __syncthreads();
    }

#pragma unroll
    for (int i = 0; i < 4; i++) {
        const int m = m0 + (ty << 2) + i;
        const int b = m >> 11;
        const int n = m & (NSEQ - 1);
#pragma unroll
        for (int j = 0; j < 4; j++) {
            const int c = n0 + (tx << 2) + j;
            const int which = c >> 9;
            const int dd = c & 511;
            const int h = dd >> 6;
            const int dk = dd & 63;
            g_qkv[((((size_t)which * BSZ + b) * NHEAD + h) * NSEQ + n) * DK + dk] =
                acc[i][j];
        }
    }
}

// ---------------------------------------------------------------------------
// Kernel 2: flash attention with mma.sync tf32 tensor cores.
// Block: 256 thr (8 warps), Br=128 q rows, Bc=64 keys per tile.
// smem (uints): Ks[64][68] | Vs[64][68] | Psm[8][16][68] | Ms(8KB bytes)
//   Qs[128][68] (fp32) overlaps Psm region (used only before the main loop).
// Stride 68 -> (g*68+t)%32 = 4g+t : conflict-free fragment loads.
// ---------------------------------------------------------------------------
__global__ __launch_bounds__(256, 2) void attn_mma_kernel()
{
    extern __shared__ unsigned int smbuf[];
    unsigned int* Ks  = smbuf;                    // 4352 u
    unsigned int* Vs  = smbuf + 4352;             // 4352 u
    unsigned int* Psm = smbuf + 8704;             // 8704 u
    unsigned char* Ms = (unsigned char*)(smbuf + 17408);  // 8192 B
    float* Qs = (float*)(smbuf + 8704);           // overlap with Psm

    const int tid  = threadIdx.x;
    const int w    = tid >> 5;
    const int lane = tid & 31;
    const int g    = lane >> 2;
    const int t    = lane & 3;
    const int qrow0 = blockIdx.x << 7;
    const int bh = blockIdx.y;
    const int b = bh >> 3, h = bh & 7;

    const float* Qg = g_qkv + (size_t)bh * NSEQ * DK;
    const float* Kg = g_qkv + (size_t)(BH + bh) * NSEQ * DK;
    const float* Vg = g_qkv + (size_t)(2 * BH + bh) * NSEQ * DK;

    // ---- stage Q tile (128 x 64) into Qs, then extract tf32 A-fragments ----
    for (int e = tid; e < 2048; e += 256) {
        const int row = e >> 4, d4 = (e & 15) << 2;
        float4 v = *(const float4*)&Qg[(size_t)(qrow0 + row) * DK + d4];
        Qs[row * 68 + d4 + 0] = v.x; Qs[row * 68 + d4 + 1] = v.y;
        Qs[row * 68 + d4 + 2] = v.z; Qs[row * 68 + d4 + 3] = v.w;
    }
    __syncthreads();

    const int r0 = w * 16 + g;                    // local q-row (0..127)
    unsigned int qf[8][4];
#pragma unroll
    for (int kt = 0; kt < 8; kt++) {
        qf[kt][0] = f2tf(Qs[r0 * 68 + kt * 8 + t]);
        qf[kt][1] = f2tf(Qs[(r0 + 8) * 68 + kt * 8 + t]);
        qf[kt][2] = f2tf(Qs[r0 * 68 + kt * 8 + t + 4]);
        qf[kt][3] = f2tf(Qs[(r0 + 8) * 68 + kt * 8 + t + 4]);
    }

    float Oa[8][4] = {};
    float mrow[2] = {-1e30f, -1e30f};
    float lrow[2] = {0.f, 0.f};

    for (int kti = 0; kti < NSEQ / 64; kti++) {
        const int kcol0 = kti << 6;
        __syncthreads();   // previous consumers done (also covers Qs reads, iter 0)

        // ---- load K, V tiles (converted to tf32 bits) + mask tile ----
        for (int e = tid; e < 1024; e += 256) {
            const int row = e >> 4, d4 = (e & 15) << 2;
            float4 kv = *(const float4*)&Kg[(size_t)(kcol0 + row) * DK + d4];
            Ks[row * 68 + d4 + 0] = f2tf(kv.x); Ks[row * 68 + d4 + 1] = f2tf(kv.y);
            Ks[row * 68 + d4 + 2] = f2tf(kv.z); Ks[row * 68 + d4 + 3] = f2tf(kv.w);
            float4 vv = *(const float4*)&Vg[(size_t)(kcol0 + row) * DK + d4];
            Vs[row * 68 + d4 + 0] = f2tf(vv.x); Vs[row * 68 + d4 + 1] = f2tf(vv.y);
            Vs[row * 68 + d4 + 2] = f2tf(vv.z); Vs[row * 68 + d4 + 3] = f2tf(vv.w);
        }
        const uint4* Mg4 = (const uint4*)(g_mask8 +
            ((size_t)b * NSEQ + qrow0) * NSEQ + kcol0);
        for (int e = tid; e < 512; e += 256) {
            const int row = e >> 2, q = e & 3;
            ((uint4*)Ms)[row * 4 + q] = Mg4[(size_t)row * (NSEQ / 16) + q];
        }
        __syncthreads();

        // ---- S = Q @ K^T  (16x64 per warp) ----
        float Sa[8][4] = {};
#pragma unroll
        for (int kt = 0; kt < 8; kt++) {
#pragma unroll
            for (int nt = 0; nt < 8; nt++) {
                unsigned int b0 = Ks[(nt * 8 + g) * 68 + kt * 8 + t];
                unsigned int b1 = Ks[(nt * 8 + g) * 68 + kt * 8 + t + 4];
                mma_tf32(Sa[nt], qf[kt], b0, b1);
            }
        }

        // ---- mask + online softmax ----
        unsigned int mbits = 0;
        float rmax0 = -1e30f, rmax1 = -1e30f;
#pragma unroll
        for (int nt = 0; nt < 8; nt++) {
            const int c = nt * 8 + 2 * t;
            uchar2 m0 = *(const uchar2*)&Ms[r0 * 64 + c];
            uchar2 m1 = *(const uchar2*)&Ms[(r0 + 8) * 64 + c];
            Sa[nt][0] = m0.x ? Sa[nt][0] * 0.125f : -1e30f;
            Sa[nt][1] = m0.y ? Sa[nt][1] * 0.125f : -1e30f;
            Sa[nt][2] = m1.x ? Sa[nt][2] * 0.125f : -1e30f;
            Sa[nt][3] = m1.y ? Sa[nt][3] * 0.125f : -1e30f;
            mbits |= (m0.x ? 1u : 0u) << (nt * 4 + 0);
            mbits |= (m0.y ? 1u : 0u) << (nt * 4 + 1);
            mbits |= (m1.x ? 1u : 0u) << (nt * 4 + 2);
            mbits |= (m1.y ? 1u : 0u) << (nt * 4 + 3);
            rmax0 = fmaxf(rmax0, fmaxf(Sa[nt][0], Sa[nt][1]));
            rmax1 = fmaxf(rmax1, fmaxf(Sa[nt][2], Sa[nt][3]));
        }
        rmax0 = fmaxf(rmax0, __shfl_xor_sync(0xffffffffu, rmax0, 1));
        rmax0 = fmaxf(rmax0, __shfl_xor_sync(0xffffffffu, rmax0, 2));
        rmax1 = fmaxf(rmax1, __shfl_xor_sync(0xffffffffu, rmax1, 1));
        rmax1 = fmaxf(rmax1, __shfl_xor_sync(0xffffffffu, rmax1, 2));

        const float mnew0 = fmaxf(mrow[0], rmax0);
        const float mnew1 = fmaxf(mrow[1], rmax1);
        const float alpha0 = __expf(mrow[0] - mnew0);
        const float alpha1 = __expf(mrow[1] - mnew1);
        mrow[0] = mnew0; mrow[1] = mnew1;

        float rsum0 = 0.f, rsum1 = 0.f;
        const unsigned int pbase = w * 1088 + g * 68 + 2 * t;
#pragma unroll
        for (int nt = 0; nt < 8; nt++) {
            const float p0 = ((mbits >> (nt * 4 + 0)) & 1u) ? __expf(Sa[nt][0] - mnew0) : 0.f;
            const float p1 = ((mbits >> (nt * 4 + 1)) & 1u) ? __expf(Sa[nt][1] - mnew0) : 0.f;
            const float p2 = ((mbits >> (nt * 4 + 2)) & 1u) ? __expf(Sa[nt][2] - mnew1) : 0.f;
            const float p3 = ((mbits >> (nt * 4 + 3)) & 1u) ? __expf(Sa[nt][3] - mnew1) : 0.f;
            rsum0 += p0 + p1; rsum1 += p2 + p3;
            uint2 u01 = make_uint2(f2tf(p0), f2tf(p1));
            uint2 u23 = make_uint2(f2tf(p2), f2tf(p3));
            *(uint2*)&Psm[pbase + nt * 8] = u01;
            *(uint2*)&Psm[pbase + 8 * 68 + nt * 8] = u23;
            Oa[nt][0] *= alpha0; Oa[nt][1] *= alpha0;
            Oa[nt][2] *= alpha1; Oa[nt][3] *= alpha1;
        }
        rsum0 += __shfl_xor_sync(0xffffffffu, rsum0, 1);
        rsum0 += __shfl_xor_sync(0xffffffffu, rsum0, 2);
        rsum1 += __shfl_xor_sync(0xffffffffu, rsum1, 1);
        rsum1 += __shfl_xor_sync(0xffffffffu, rsum1, 2);
        lrow[0] = lrow[0] * alpha0 + rsum0;
        lrow[1] = lrow[1] * alpha1 + rsum1;

        __syncwarp();   // Psm stores visible to all lanes of this warp

        // ---- O += P @ V ----
        const unsigned int wb = w * 1088;
#pragma unroll
        for (int kt = 0; kt < 8; kt++) {
            unsigned int a[4];
            a[0] = Psm[wb + g * 68 + kt * 8 + t];
            a[1] = Psm[wb + (g + 8) * 68 + kt * 8 + t];
            a[2] = Psm[wb + g * 68 + kt * 8 + t + 4];
            a[3] = Psm[wb + (g + 8) * 68 + kt * 8 + t + 4];
#pragma unroll
            for (int nt = 0; nt < 8; nt++) {
                unsigned int b0 = Vs[(kt * 8 + t) * 68 + nt * 8 + g];
                unsigned int b1 = Vs[(kt * 8 + t + 4) * 68 + nt * 8 + g];
                mma_tf32(Oa[nt], a, b0, b1);
            }
        }
    }

    // ---- epilogue: normalize and write [B][N][D] ----
    const float inv0 = 1.f / lrow[0];
    const float inv1 = 1.f / lrow[1];
    const int grow = qrow0 + r0;
#pragma unroll
    for (int nt = 0; nt < 8; nt++) {
        const int c = h * 64 + nt * 8 + 2 * t;
        *(float2*)&g_att[((size_t)b * NSEQ + grow) * DMODEL + c] =
            make_float2(Oa[nt][0] * inv0, Oa[nt][1] * inv0);
        *(float2*)&g_att[((size_t)b * NSEQ + grow + 8) * DMODEL + c] =
            make_float2(Oa[nt][2] * inv1, Oa[nt][3] * inv1);
    }
}

// ---------------------------------------------------------------------------
// Kernel 3: output projection + bias + LeakyReLU (fp32 scalar).
// ---------------------------------------------------------------------------
__global__ __launch_bounds__(256) void out_gemm_kernel(
    const float* __restrict__ W, const float* __restrict__ bias,
    float* __restrict__ out)
{
    __shared__ float As[16][64];
    __shared__ float Bs[16][64];

    const int tid = threadIdx.x;
    const int tx = tid & 15, ty = tid >> 4;
    const int n0 = blockIdx.x << 6;
    const int m0 = blockIdx.y << 6;

    float acc[4][4] = {};

    const int ar = tid >> 2, ak = (tid & 3) << 2;
    const int bk = tid >> 4, bc = (tid & 15) << 2;
    const float* Xp = g_att + (size_t)(m0 + ar) * DMODEL + ak;
    const float* Wp = W + (size_t)bk * DMODEL + n0 + bc;

    for (int k0 = 0; k0 < DMODEL; k0 += 16) {
        float4 av = *(const float4*)(Xp + k0);
        As[ak + 0][ar] = av.x; As[ak + 1][ar] = av.y;
        As[ak + 2][ar] = av.z; As[ak + 3][ar] = av.w;
        *(float4*)&Bs[bk][bc] = *(const float4*)(Wp + (size_t)k0 * DMODEL);
        __syncthreads();
#pragma unroll
        for (int kk = 0; kk < 16; kk++) {
            float4 a4 = *(const float4*)&As[kk][ty << 2];
            float4 b4 = *(const float4*)&Bs[kk][tx << 2];
            float a[4] = {a4.x, a4.y, a4.z, a4.w};
            float b[4] = {b4.x, b4.y, b4.z, b4.w};
#pragma unroll
            for (int i = 0; i < 4; i++)
#pragma unroll
                for (int j = 0; j < 4; j++) acc[i][j] += a[i] * b[j];
        }
        __syncthreads();
    }

#pragma unroll
    for (int i = 0; i < 4; i++) {
        const int m = m0 + (ty << 2) + i;
#pragma unroll
        for (int j = 0; j < 4; j++) {
            const int c = n0 + (tx << 2) + j;
            float v = acc[i][j] + bias[c];
            out[(size_t)m * DMODEL + c] = (v >= 0.f) ? v : 0.1f * v;
        }
    }
}

// ---------------------------------------------------------------------------
extern "C" void kernel_launch(void* const* d_in, const int* in_sizes, int n_in,
                              void* d_out, int out_size)
{
    const float* x = nullptr;
    const void* mask = nullptr;
    const float* Wqkv = nullptr;
    const float* Wout = nullptr;
    const float* bout = nullptr;
    for (int i = 0; i < n_in; i++) {
        switch (in_sizes[i]) {
            case 4194304:  x    = (const float*)d_in[i]; break;
            case 16777216: mask = d_in[i];               break;
            case 786432:   Wqkv = (const float*)d_in[i]; break;
            case 262144:   Wout = (const float*)d_in[i]; break;
            case 512:      bout = (const float*)d_in[i]; break;
        }
    }
    float* out = (float*)d_out;

    cudaFuncSetAttribute(attn_mma_kernel,
                         cudaFuncAttributeMaxDynamicSharedMemorySize, 77824);

    mask_detect_kernel<<<1, 256>>>((const unsigned int*)mask);
    mask_convert_kernel<<<(unsigned)((MASK_ELEMS + 255) / 256), 256>>>(mask);
    qkv_gemm_kernel<<<dim3(THREE_D / 64, M_ROWS / 64), 256>>>(x, Wqkv);
    attn_mma_kernel<<<dim3(NSEQ / 128, BH), 256, 77824>>>();
    out_gemm_kernel<<<dim3(DMODEL / 64, M_ROWS / 64), 256>>>(Wout, bout, out);
}

// round 7
// speedup vs baseline: 2.3209x; 1.2873x over previous
#include <cuda_runtime.h>
#include <cstdint>

#define BSZ 4
#define NSEQ 2048
#define DMODEL 512
#define NHEAD 8
#define DK 64
#define BH (BSZ * NHEAD)          // 32
#define M_ROWS (BSZ * NSEQ)       // 8192
#define THREE_D (3 * DMODEL)      // 1536
#define MASK_ELEMS ((size_t)BSZ * NSEQ * NSEQ)   // 16,777,216

// Scratch
__device__ float g_qkv[(size_t)3 * BH * NSEQ * DK];     // ~50 MB
__device__ float g_att[(size_t)BSZ * NSEQ * DMODEL];    // ~17 MB
__device__ unsigned char g_mask8[MASK_ELEMS];           // 16 MB
__device__ int g_mask_mode;                             // 0=u8, 1=i32, 2=f32

// ---------------------------------------------------------------------------
// tf32 helpers
// ---------------------------------------------------------------------------
__device__ __forceinline__ unsigned int f2tf(float f) {
    unsigned int u;
    asm("cvt.rna.tf32.f32 %0, %1;" : "=r"(u) : "f"(f));
    return u;
}

__device__ __forceinline__ void mma_tf32(float* c, const unsigned int* a,
                                         unsigned int b0, unsigned int b1) {
    asm volatile(
        "mma.sync.aligned.m16n8k8.row.col.f32.tf32.tf32.f32 "
        "{%0,%1,%2,%3}, {%4,%5,%6,%7}, {%8,%9}, {%0,%1,%2,%3};"
        : "+f"(c[0]), "+f"(c[1]), "+f"(c[2]), "+f"(c[3])
        : "r"(a[0]), "r"(a[1]), "r"(a[2]), "r"(a[3]), "r"(b0), "r"(b1));
}

// ---------------------------------------------------------------------------
// Kernel 0a/0b: mask dtype detect + normalize to uint8
// ---------------------------------------------------------------------------
__global__ void mask_detect_kernel(const unsigned int* __restrict__ m)
{
    __shared__ int sawBig, sawFloatOne;
    if (threadIdx.x == 0) { sawBig = 0; sawFloatOne = 0; }
    __syncthreads();
    for (int i = threadIdx.x; i < 16384; i += blockDim.x) {
        unsigned int w = m[i];
        if (w == 0x3F800000u) atomicOr(&sawFloatOne, 1);
        else if (w > 1u) atomicOr(&sawBig, 1);
    }
    __syncthreads();
    if (threadIdx.x == 0)
        g_mask_mode = sawFloatOne ? 2 : (sawBig ? 0 : 1);
}

__global__ __launch_bounds__(256) void mask_convert_kernel(const void* __restrict__ m)
{
    const size_t i = (size_t)blockIdx.x * blockDim.x + threadIdx.x;
    if (i >= MASK_ELEMS) return;
    const int mode = g_mask_mode;
    unsigned char v;
    if (mode == 0)      v = ((const unsigned char*)m)[i] != 0;
    else if (mode == 1) v = ((const int*)m)[i] != 0;
    else                v = ((const float*)m)[i] != 0.0f;
    g_mask8[i] = v;
}

// ---------------------------------------------------------------------------
// TF32 MMA GEMM core: 128(m) x 64(n) block tile, BK=16, 8 warps each m16 x n64,
// double-buffered smem. AEXPR is a device-side pointer expression for A.
// ---------------------------------------------------------------------------
#define GEMM_BODY(AEXPR, LDA, LDB, KDIM)                                       \
    const float* __restrict__ A = (AEXPR);                                     \
    __shared__ unsigned int As[2][128][20];                                    \
    __shared__ unsigned int Bs[2][16][68];                                     \
    const int tid = threadIdx.x;                                               \
    const int w = tid >> 5, lane = tid & 31;                                   \
    const int g = lane >> 2, t = lane & 3;                                     \
    const int n0 = blockIdx.x << 6, m0 = blockIdx.y << 7;                      \
    const int ar = tid >> 2, ak4 = (tid & 3) << 2;                             \
    const int bk = tid >> 4, bn4 = (tid & 15) << 2;                            \
    float acc[8][4] = {};                                                      \
    float4 pa0, pa1, pb0;                                                      \
    pa0 = *(const float4*)&A[(size_t)(m0 + ar) * LDA + ak4];                   \
    pa1 = *(const float4*)&A[(size_t)(m0 + ar + 64) * LDA + ak4];              \
    pb0 = *(const float4*)&Bm[(size_t)bk * LDB + n0 + bn4];                    \
    {                                                                          \
        unsigned int* a0 = &As[0][ar][ak4];                                    \
        a0[0] = f2tf(pa0.x); a0[1] = f2tf(pa0.y);                              \
        a0[2] = f2tf(pa0.z); a0[3] = f2tf(pa0.w);                              \
        unsigned int* a1 = &As[0][ar + 64][ak4];                               \
        a1[0] = f2tf(pa1.x); a1[1] = f2tf(pa1.y);                              \
        a1[2] = f2tf(pa1.z); a1[3] = f2tf(pa1.w);                              \
        unsigned int* b0p = &Bs[0][bk][bn4];                                   \
        b0p[0] = f2tf(pb0.x); b0p[1] = f2tf(pb0.y);                            \
        b0p[2] = f2tf(pb0.z); b0p[3] = f2tf(pb0.w);                            \
    }                                                                          \
    __syncthreads();                                                           \
    const int NS = (KDIM) / 16;                                                \
    for (int s = 0; s < NS; s++) {                                             \
        const int cur = s & 1;                                                 \
        if (s + 1 < NS) {                                                      \
            const int k0 = (s + 1) << 4;                                       \
            pa0 = *(const float4*)&A[(size_t)(m0 + ar) * LDA + k0 + ak4];      \
            pa1 = *(const float4*)&A[(size_t)(m0 + ar + 64) * LDA + k0 + ak4]; \
            pb0 = *(const float4*)&Bm[(size_t)(k0 + bk) * LDB + n0 + bn4];     \
        }                                                                      \
        _Pragma("unroll")                                                      \
        for (int kt = 0; kt < 2; kt++) {                                       \
            unsigned int a[4];                                                 \
            a[0] = As[cur][w * 16 + g][kt * 8 + t];                            \
            a[1] = As[cur][w * 16 + g + 8][kt * 8 + t];                        \
            a[2] = As[cur][w * 16 + g][kt * 8 + t + 4];                        \
            a[3] = As[cur][w * 16 + g + 8][kt * 8 + t + 4];                    \
            _Pragma("unroll")                                                  \
            for (int nt = 0; nt < 8; nt++) {                                   \
                unsigned int b0 = Bs[cur][kt * 8 + t][nt * 8 + g];             \
                unsigned int b1 = Bs[cur][kt * 8 + t + 4][nt * 8 + g];         \
                mma_tf32(acc[nt], a, b0, b1);                                  \
            }                                                                  \
        }                                                                      \
        if (s + 1 < NS) {                                                      \
            const int nxt = cur ^ 1;                                           \
            unsigned int* a0 = &As[nxt][ar][ak4];                              \
            a0[0] = f2tf(pa0.x); a0[1] = f2tf(pa0.y);                          \
            a0[2] = f2tf(pa0.z); a0[3] = f2tf(pa0.w);                          \
            unsigned int* a1 = &As[nxt][ar + 64][ak4];                         \
            a1[0] = f2tf(pa1.x); a1[1] = f2tf(pa1.y);                          \
            a1[2] = f2tf(pa1.z); a1[3] = f2tf(pa1.w);                          \
            unsigned int* b0p = &Bs[nxt][bk][bn4];                             \
            b0p[0] = f2tf(pb0.x); b0p[1] = f2tf(pb0.y);                        \
            b0p[2] = f2tf(pb0.z); b0p[3] = f2tf(pb0.w);                        \
        }                                                                      \
        __syncthreads();                                                       \
    }

// ---------------------------------------------------------------------------
// Kernel 1: QKV projection via tf32 mma, scatter epilogue into g_qkv.
// ---------------------------------------------------------------------------
__global__ __launch_bounds__(256, 2) void qkv_mma_kernel(
    const float* __restrict__ X, const float* __restrict__ Bm)
{
    GEMM_BODY(X, DMODEL, THREE_D, DMODEL)

    const int r0 = w * 16 + g;
#pragma unroll
    for (int nt = 0; nt < 8; nt++) {
        const int c = n0 + nt * 8 + 2 * t;
        const int which = c >> 9;
        const int dd = c & 511;
        const int h = dd >> 6;
        const int dk = dd & 63;
#pragma unroll
        for (int half = 0; half < 2; half++) {
            const int m = m0 + r0 + half * 8;
            const int b = m >> 11;
            const int n = m & (NSEQ - 1);
            *(float2*)&g_qkv[((((size_t)which * BSZ + b) * NHEAD + h) * NSEQ + n)
                             * DK + dk] =
                make_float2(acc[nt][half * 2], acc[nt][half * 2 + 1]);
        }
    }
}

// ---------------------------------------------------------------------------
// Kernel 2: flash attention with mma.sync tf32 (unchanged, validated r3).
// ---------------------------------------------------------------------------
__global__ __launch_bounds__(256, 2) void attn_mma_kernel()
{
    extern __shared__ unsigned int smbuf[];
    unsigned int* Ks  = smbuf;                    // 4352 u
    unsigned int* Vs  = smbuf + 4352;             // 4352 u
    unsigned int* Psm = smbuf + 8704;             // 8704 u
    unsigned char* Ms = (unsigned char*)(smbuf + 17408);  // 8192 B
    float* Qs = (float*)(smbuf + 8704);           // overlap with Psm

    const int tid  = threadIdx.x;
    const int w    = tid >> 5;
    const int lane = tid & 31;
    const int g    = lane >> 2;
    const int t    = lane & 3;
    const int qrow0 = blockIdx.x << 7;
    const int bh = blockIdx.y;
    const int b = bh >> 3, h = bh & 7;

    const float* Qg = g_qkv + (size_t)bh * NSEQ * DK;
    const float* Kg = g_qkv + (size_t)(BH + bh) * NSEQ * DK;
    const float* Vg = g_qkv + (size_t)(2 * BH + bh) * NSEQ * DK;

    for (int e = tid; e < 2048; e += 256) {
        const int row = e >> 4, d4 = (e & 15) << 2;
        float4 v = *(const float4*)&Qg[(size_t)(qrow0 + row) * DK + d4];
        Qs[row * 68 + d4 + 0] = v.x; Qs[row * 68 + d4 + 1] = v.y;
        Qs[row * 68 + d4 + 2] = v.z; Qs[row * 68 + d4 + 3] = v.w;
    }
    __syncthreads();

    const int r0 = w * 16 + g;
    unsigned int qf[8][4];
#pragma unroll
    for (int kt = 0; kt < 8; kt++) {
        qf[kt][0] = f2tf(Qs[r0 * 68 + kt * 8 + t]);
        qf[kt][1] = f2tf(Qs[(r0 + 8) * 68 + kt * 8 + t]);
        qf[kt][2] = f2tf(Qs[r0 * 68 + kt * 8 + t + 4]);
        qf[kt][3] = f2tf(Qs[(r0 + 8) * 68 + kt * 8 + t + 4]);
    }

    float Oa[8][4] = {};
    float mrow[2] = {-1e30f, -1e30f};
    float lrow[2] = {0.f, 0.f};

    for (int kti = 0; kti < NSEQ / 64; kti++) {
        const int kcol0 = kti << 6;
        __syncthreads();

        for (int e = tid; e < 1024; e += 256) {
            const int row = e >> 4, d4 = (e & 15) << 2;
            float4 kv = *(const float4*)&Kg[(size_t)(kcol0 + row) * DK + d4];
            Ks[row * 68 + d4 + 0] = f2tf(kv.x); Ks[row * 68 + d4 + 1] = f2tf(kv.y);
            Ks[row * 68 + d4 + 2] = f2tf(kv.z); Ks[row * 68 + d4 + 3] = f2tf(kv.w);
            float4 vv = *(const float4*)&Vg[(size_t)(kcol0 + row) * DK + d4];
            Vs[row * 68 + d4 + 0] = f2tf(vv.x); Vs[row * 68 + d4 + 1] = f2tf(vv.y);
            Vs[row * 68 + d4 + 2] = f2tf(vv.z); Vs[row * 68 + d4 + 3] = f2tf(vv.w);
        }
        const uint4* Mg4 = (const uint4*)(g_mask8 +
            ((size_t)b * NSEQ + qrow0) * NSEQ + kcol0);
        for (int e = tid; e < 512; e += 256) {
            const int row = e >> 2, q = e & 3;
            ((uint4*)Ms)[row * 4 + q] = Mg4[(size_t)row * (NSEQ / 16) + q];
        }
        __syncthreads();

        float Sa[8][4] = {};
#pragma unroll
        for (int kt = 0; kt < 8; kt++) {
#pragma unroll
            for (int nt = 0; nt < 8; nt++) {
                unsigned int b0 = Ks[(nt * 8 + g) * 68 + kt * 8 + t];
                unsigned int b1 = Ks[(nt * 8 + g) * 68 + kt * 8 + t + 4];
                mma_tf32(Sa[nt], qf[kt], b0, b1);
            }
        }

        unsigned int mbits = 0;
        float rmax0 = -1e30f, rmax1 = -1e30f;
#pragma unroll
        for (int nt = 0; nt < 8; nt++) {
            const int c = nt * 8 + 2 * t;
            uchar2 m0 = *(const uchar2*)&Ms[r0 * 64 + c];
            uchar2 m1 = *(const uchar2*)&Ms[(r0 + 8) * 64 + c];
            Sa[nt][0] = m0.x ? Sa[nt][0] * 0.125f : -1e30f;
            Sa[nt][1] = m0.y ? Sa[nt][1] * 0.125f : -1e30f;
            Sa[nt][2] = m1.x ? Sa[nt][2] * 0.125f : -1e30f;
            Sa[nt][3] = m1.y ? Sa[nt][3] * 0.125f : -1e30f;
            mbits |= (m0.x ? 1u : 0u) << (nt * 4 + 0);
            mbits |= (m0.y ? 1u : 0u) << (nt * 4 + 1);
            mbits |= (m1.x ? 1u : 0u) << (nt * 4 + 2);
            mbits |= (m1.y ? 1u : 0u) << (nt * 4 + 3);
            rmax0 = fmaxf(rmax0, fmaxf(Sa[nt][0], Sa[nt][1]));
            rmax1 = fmaxf(rmax1, fmaxf(Sa[nt][2], Sa[nt][3]));
        }
        rmax0 = fmaxf(rmax0, __shfl_xor_sync(0xffffffffu, rmax0, 1));
        rmax0 = fmaxf(rmax0, __shfl_xor_sync(0xffffffffu, rmax0, 2));
        rmax1 = fmaxf(rmax1, __shfl_xor_sync(0xffffffffu, rmax1, 1));
        rmax1 = fmaxf(rmax1, __shfl_xor_sync(0xffffffffu, rmax1, 2));

        const float mnew0 = fmaxf(mrow[0], rmax0);
        const float mnew1 = fmaxf(mrow[1], rmax1);
        const float alpha0 = __expf(mrow[0] - mnew0);
        const float alpha1 = __expf(mrow[1] - mnew1);
        mrow[0] = mnew0; mrow[1] = mnew1;

        float rsum0 = 0.f, rsum1 = 0.f;
        const unsigned int pbase = w * 1088 + g * 68 + 2 * t;
#pragma unroll
        for (int nt = 0; nt < 8; nt++) {
            const float p0 = ((mbits >> (nt * 4 + 0)) & 1u) ? __expf(Sa[nt][0] - mnew0) : 0.f;
            const float p1 = ((mbits >> (nt * 4 + 1)) & 1u) ? __expf(Sa[nt][1] - mnew0) : 0.f;
            const float p2 = ((mbits >> (nt * 4 + 2)) & 1u) ? __expf(Sa[nt][2] - mnew1) : 0.f;
            const float p3 = ((mbits >> (nt * 4 + 3)) & 1u) ? __expf(Sa[nt][3] - mnew1) : 0.f;
            rsum0 += p0 + p1; rsum1 += p2 + p3;
            uint2 u01 = make_uint2(f2tf(p0), f2tf(p1));
            uint2 u23 = make_uint2(f2tf(p2), f2tf(p3));
            *(uint2*)&Psm[pbase + nt * 8] = u01;
            *(uint2*)&Psm[pbase + 8 * 68 + nt * 8] = u23;
            Oa[nt][0] *= alpha0; Oa[nt][1] *= alpha0;
            Oa[nt][2] *= alpha1; Oa[nt][3] *= alpha1;
        }
        rsum0 += __shfl_xor_sync(0xffffffffu, rsum0, 1);
        rsum0 += __shfl_xor_sync(0xffffffffu, rsum0, 2);
        rsum1 += __shfl_xor_sync(0xffffffffu, rsum1, 1);
        rsum1 += __shfl_xor_sync(0xffffffffu, rsum1, 2);
        lrow[0] = lrow[0] * alpha0 + rsum0;
        lrow[1] = lrow[1] * alpha1 + rsum1;

        __syncwarp();

        const unsigned int wb = w * 1088;
#pragma unroll
        for (int kt = 0; kt < 8; kt++) {
            unsigned int a[4];
            a[0] = Psm[wb + g * 68 + kt * 8 + t];
            a[1] = Psm[wb + (g + 8) * 68 + kt * 8 + t];
            a[2] = Psm[wb + g * 68 + kt * 8 + t + 4];
            a[3] = Psm[wb + (g + 8) * 68 + kt * 8 + t + 4];
#pragma unroll
            for (int nt = 0; nt < 8; nt++) {
                unsigned int b0 = Vs[(kt * 8 + t) * 68 + nt * 8 + g];
                unsigned int b1 = Vs[(kt * 8 + t + 4) * 68 + nt * 8 + g];
                mma_tf32(Oa[nt], a, b0, b1);
            }
        }
    }

    const float inv0 = 1.f / lrow[0];
    const float inv1 = 1.f / lrow[1];
    const int grow = qrow0 + r0;
#pragma unroll
    for (int nt = 0; nt < 8; nt++) {
        const int c = h * 64 + nt * 8 + 2 * t;
        *(float2*)&g_att[((size_t)b * NSEQ + grow) * DMODEL + c] =
            make_float2(Oa[nt][0] * inv0, Oa[nt][1] * inv0);
        *(float2*)&g_att[((size_t)b * NSEQ + grow + 8) * DMODEL + c] =
            make_float2(Oa[nt][2] * inv1, Oa[nt][3] * inv1);
    }
}

// ---------------------------------------------------------------------------
// Kernel 3: output projection via tf32 mma + bias + LeakyReLU.
// A = g_att referenced in DEVICE code (never passed from host).
// ---------------------------------------------------------------------------
__global__ __launch_bounds__(256, 2) void out_mma_kernel(
    const float* __restrict__ Bm, const float* __restrict__ bias,
    float* __restrict__ out)
{
    GEMM_BODY((const float*)g_att, DMODEL, DMODEL, DMODEL)

    const int r0 = w * 16 + g;
#pragma unroll
    for (int nt = 0; nt < 8; nt++) {
        const int c = n0 + nt * 8 + 2 * t;
        const float b0 = bias[c], b1 = bias[c + 1];
#pragma unroll
        for (int half = 0; half < 2; half++) {
            const int m = m0 + r0 + half * 8;
            float v0 = acc[nt][half * 2] + b0;
            float v1 = acc[nt][half * 2 + 1] + b1;
            v0 = (v0 >= 0.f) ? v0 : 0.1f * v0;
            v1 = (v1 >= 0.f) ? v1 : 0.1f * v1;
            *(float2*)&out[(size_t)m * DMODEL + c] = make_float2(v0, v1);
        }
    }
}

// ---------------------------------------------------------------------------
extern "C" void kernel_launch(void* const* d_in, const int* in_sizes, int n_in,
                              void* d_out, int out_size)
{
    const float* x = nullptr;
    const void* mask = nullptr;
    const float* Wqkv = nullptr;
    const float* Wout = nullptr;
    const float* bout = nullptr;
    for (int i = 0; i < n_in; i++) {
        switch (in_sizes[i]) {
            case 4194304:  x    = (const float*)d_in[i]; break;
            case 16777216: mask = d_in[i];               break;
            case 786432:   Wqkv = (const float*)d_in[i]; break;
            case 262144:   Wout = (const float*)d_in[i]; break;
            case 512:      bout = (const float*)d_in[i]; break;
        }
    }
    float* out = (float*)d_out;

    cudaFuncSetAttribute(attn_mma_kernel,
                         cudaFuncAttributeMaxDynamicSharedMemorySize, 77824);

    mask_detect_kernel<<<1, 256>>>((const unsigned int*)mask);
    mask_convert_kernel<<<(unsigned)((MASK_ELEMS + 255) / 256), 256>>>(mask);
    qkv_mma_kernel<<<dim3(THREE_D / 64, M_ROWS / 128), 256>>>(x, Wqkv);
    attn_mma_kernel<<<dim3(NSEQ / 128, BH), 256, 77824>>>();
    out_mma_kernel<<<dim3(DMODEL / 64, M_ROWS / 128), 256>>>(Wout, bout, out);
}

// round 8
// speedup vs baseline: 2.3357x; 1.0064x over previous
#include <cuda_runtime.h>
#include <cstdint>

#define BSZ 4
#define NSEQ 2048
#define DMODEL 512
#define NHEAD 8
#define DK 64
#define BH (BSZ * NHEAD)          // 32
#define M_ROWS (BSZ * NSEQ)       // 8192
#define THREE_D (3 * DMODEL)      // 1536
#define MASK_ELEMS ((size_t)BSZ * NSEQ * NSEQ)   // 16,777,216
#define KSTR 72                   // padded row stride for attn smem tiles

// Scratch
__device__ float g_qkv[(size_t)3 * BH * NSEQ * DK];     // ~50 MB
__device__ float g_att[(size_t)BSZ * NSEQ * DMODEL];    // ~17 MB
__device__ unsigned char g_mask8[MASK_ELEMS];           // 16 MB
__device__ int g_mask_mode;                             // 0=u8, 1=i32, 2=f32

// ---------------------------------------------------------------------------
// tf32 helpers
// ---------------------------------------------------------------------------
__device__ __forceinline__ unsigned int f2tf(float f) {
    unsigned int u;
    asm("cvt.rna.tf32.f32 %0, %1;" : "=r"(u) : "f"(f));
    return u;
}

__device__ __forceinline__ void mma_tf32(float* c, const unsigned int* a,
                                         unsigned int b0, unsigned int b1) {
    asm volatile(
        "mma.sync.aligned.m16n8k8.row.col.f32.tf32.tf32.f32 "
        "{%0,%1,%2,%3}, {%4,%5,%6,%7}, {%8,%9}, {%0,%1,%2,%3};"
        : "+f"(c[0]), "+f"(c[1]), "+f"(c[2]), "+f"(c[3])
        : "r"(a[0]), "r"(a[1]), "r"(a[2]), "r"(a[3]), "r"(b0), "r"(b1));
}

// ---------------------------------------------------------------------------
// Kernel 0a/0b: mask dtype detect + normalize to uint8
// ---------------------------------------------------------------------------
__global__ void mask_detect_kernel(const unsigned int* __restrict__ m)
{
    __shared__ int sawBig, sawFloatOne;
    if (threadIdx.x == 0) { sawBig = 0; sawFloatOne = 0; }
    __syncthreads();
    for (int i = threadIdx.x; i < 16384; i += blockDim.x) {
        unsigned int w = m[i];
        if (w == 0x3F800000u) atomicOr(&sawFloatOne, 1);
        else if (w > 1u) atomicOr(&sawBig, 1);
    }
    __syncthreads();
    if (threadIdx.x == 0)
        g_mask_mode = sawFloatOne ? 2 : (sawBig ? 0 : 1);
}

__global__ __launch_bounds__(256) void mask_convert_kernel(const void* __restrict__ m)
{
    const size_t i = (size_t)blockIdx.x * blockDim.x + threadIdx.x;
    if (i >= MASK_ELEMS) return;
    const int mode = g_mask_mode;
    unsigned char v;
    if (mode == 0)      v = ((const unsigned char*)m)[i] != 0;
    else if (mode == 1) v = ((const int*)m)[i] != 0;
    else                v = ((const float*)m)[i] != 0.0f;
    g_mask8[i] = v;
}

// ---------------------------------------------------------------------------
// TF32 MMA GEMM core: 128(m) x 64(n) block tile, BK=16, 8 warps each m16 x n64,
// double-buffered smem. AEXPR is a device-side pointer expression for A.
// ---------------------------------------------------------------------------
#define GEMM_BODY(AEXPR, LDA, LDB, KDIM)                                       \
    const float* __restrict__ A = (AEXPR);                                     \
    __shared__ unsigned int As[2][128][20];                                    \
    __shared__ unsigned int Bs[2][16][68];                                     \
    const int tid = threadIdx.x;                                               \
    const int w = tid >> 5, lane = tid & 31;                                   \
    const int g = lane >> 2, t = lane & 3;                                     \
    const int n0 = blockIdx.x << 6, m0 = blockIdx.y << 7;                      \
    const int ar = tid >> 2, ak4 = (tid & 3) << 2;                             \
    const int bk = tid >> 4, bn4 = (tid & 15) << 2;                            \
    float acc[8][4] = {};                                                      \
    float4 pa0, pa1, pb0;                                                      \
    pa0 = *(const float4*)&A[(size_t)(m0 + ar) * LDA + ak4];                   \
    pa1 = *(const float4*)&A[(size_t)(m0 + ar + 64) * LDA + ak4];              \
    pb0 = *(const float4*)&Bm[(size_t)bk * LDB + n0 + bn4];                    \
    {                                                                          \
        unsigned int* a0 = &As[0][ar][ak4];                                    \
        a0[0] = f2tf(pa0.x); a0[1] = f2tf(pa0.y);                              \
        a0[2] = f2tf(pa0.z); a0[3] = f2tf(pa0.w);                              \
        unsigned int* a1 = &As[0][ar + 64][ak4];                               \
        a1[0] = f2tf(pa1.x); a1[1] = f2tf(pa1.y);                              \
        a1[2] = f2tf(pa1.z); a1[3] = f2tf(pa1.w);                              \
        unsigned int* b0p = &Bs[0][bk][bn4];                                   \
        b0p[0] = f2tf(pb0.x); b0p[1] = f2tf(pb0.y);                            \
        b0p[2] = f2tf(pb0.z); b0p[3] = f2tf(pb0.w);                            \
    }                                                                          \
    __syncthreads();                                                           \
    const int NS = (KDIM) / 16;                                                \
    for (int s = 0; s < NS; s++) {                                             \
        const int cur = s & 1;                                                 \
        if (s + 1 < NS) {                                                      \
            const int k0 = (s + 1) << 4;                                       \
            pa0 = *(const float4*)&A[(size_t)(m0 + ar) * LDA + k0 + ak4];      \
            pa1 = *(const float4*)&A[(size_t)(m0 + ar + 64) * LDA + k0 + ak4]; \
            pb0 = *(const float4*)&Bm[(size_t)(k0 + bk) * LDB + n0 + bn4];     \
        }                                                                      \
        _Pragma("unroll")                                                      \
        for (int kt = 0; kt < 2; kt++) {                                       \
            unsigned int a[4];                                                 \
            a[0] = As[cur][w * 16 + g][kt * 8 + t];                            \
            a[1] = As[cur][w * 16 + g + 8][kt * 8 + t];                        \
            a[2] = As[cur][w * 16 + g][kt * 8 + t + 4];                        \
            a[3] = As[cur][w * 16 + g + 8][kt * 8 + t + 4];                    \
            _Pragma("unroll")                                                  \
            for (int nt = 0; nt < 8; nt++) {                                   \
                unsigned int b0 = Bs[cur][kt * 8 + t][nt * 8 + g];             \
                unsigned int b1 = Bs[cur][kt * 8 + t + 4][nt * 8 + g];         \
                mma_tf32(acc[nt], a, b0, b1);                                  \
            }                                                                  \
        }                                                                      \
        if (s + 1 < NS) {                                                      \
            const int nxt = cur ^ 1;                                           \
            unsigned int* a0 = &As[nxt][ar][ak4];                              \
            a0[0] = f2tf(pa0.x); a0[1] = f2tf(pa0.y);                          \
            a0[2] = f2tf(pa0.z); a0[3] = f2tf(pa0.w);                          \
            unsigned int* a1 = &As[nxt][ar + 64][ak4];                         \
            a1[0] = f2tf(pa1.x); a1[1] = f2tf(pa1.y);                          \
            a1[2] = f2tf(pa1.z); a1[3] = f2tf(pa1.w);                          \
            unsigned int* b0p = &Bs[nxt][bk][bn4];                             \
            b0p[0] = f2tf(pb0.x); b0p[1] = f2tf(pb0.y);                        \
            b0p[2] = f2tf(pb0.z); b0p[3] = f2tf(pb0.w);                        \
        }                                                                      \
        __syncthreads();                                                       \
    }

// ---------------------------------------------------------------------------
// Kernel 1: QKV projection via tf32 mma, scatter epilogue into g_qkv.
// ---------------------------------------------------------------------------
__global__ __launch_bounds__(256, 2) void qkv_mma_kernel(
    const float* __restrict__ X, const float* __restrict__ Bm)
{
    GEMM_BODY(X, DMODEL, THREE_D, DMODEL)

    const int r0 = w * 16 + g;
#pragma unroll
    for (int nt = 0; nt < 8; nt++) {
        const int c = n0 + nt * 8 + 2 * t;
        const int which = c >> 9;
        const int dd = c & 511;
        const int h = dd >> 6;
        const int dk = dd & 63;
#pragma unroll
        for (int half = 0; half < 2; half++) {
            const int m = m0 + r0 + half * 8;
            const int b = m >> 11;
            const int n = m & (NSEQ - 1);
            *(float2*)&g_qkv[((((size_t)which * BSZ + b) * NHEAD + h) * NSEQ + n)
                             * DK + dk] =
                make_float2(acc[nt][half * 2], acc[nt][half * 2 + 1]);
        }
    }
}

// ---------------------------------------------------------------------------
// Kernel 2: flash attention, tf32 mma, PERMUTED k-dim smem layout.
// pcol(d) = (d&~7) | ((d&3)<<1) | ((d>>2)&1): places k=t and k=t+4 adjacent,
// so every fragment pair is one lds.64. Row stride KSTR=72 -> fragment loads
// conflict-free per 16-lane phase.
// smem (u32): Ks[64][72] | Vt[64][72] (dk-major, key permuted) |
//             Psm[8][16][72] | Ms (8KB). Qs overlaps Psm (pre-loop only).
// ---------------------------------------------------------------------------
__global__ __launch_bounds__(256, 2) void attn_mma_kernel()
{
    extern __shared__ unsigned int smbuf[];
    unsigned int* Ks  = smbuf;                      // 4608 u
    unsigned int* Vt  = smbuf + 4608;               // 4608 u
    unsigned int* Psm = smbuf + 9216;               // 9216 u (8 warps x 16 x 72)
    unsigned char* Ms = (unsigned char*)(smbuf + 18432);  // 8192 B
    float* Qs = (float*)(smbuf + 9216);             // overlap with Psm (8704 u)

    const int tid  = threadIdx.x;
    const int w    = tid >> 5;
    const int lane = tid & 31;
    const int g    = lane >> 2;
    const int t    = lane & 3;
    const int qrow0 = blockIdx.x << 7;
    const int bh = blockIdx.y;
    const int b = bh >> 3, h = bh & 7;

    const float* Qg = g_qkv + (size_t)bh * NSEQ * DK;
    const float* Kg = g_qkv + (size_t)(BH + bh) * NSEQ * DK;
    const float* Vg = g_qkv + (size_t)(2 * BH + bh) * NSEQ * DK;

    // ---- stage Q tile (unpermuted, stride 68), extract tf32 A-fragments ----
    for (int e = tid; e < 2048; e += 256) {
        const int row = e >> 4, d4 = (e & 15) << 2;
        float4 v = *(const float4*)&Qg[(size_t)(qrow0 + row) * DK + d4];
        Qs[row * 68 + d4 + 0] = v.x; Qs[row * 68 + d4 + 1] = v.y;
        Qs[row * 68 + d4 + 2] = v.z; Qs[row * 68 + d4 + 3] = v.w;
    }
    __syncthreads();

    const int r0 = w * 16 + g;
    unsigned int qf[8][4];
#pragma unroll
    for (int kt = 0; kt < 8; kt++) {
        qf[kt][0] = f2tf(Qs[r0 * 68 + kt * 8 + t]);
        qf[kt][1] = f2tf(Qs[(r0 + 8) * 68 + kt * 8 + t]);
        qf[kt][2] = f2tf(Qs[r0 * 68 + kt * 8 + t + 4]);
        qf[kt][3] = f2tf(Qs[(r0 + 8) * 68 + kt * 8 + t + 4]);
    }

    float Oa[8][4] = {};
    float mrow[2] = {-1e30f, -1e30f};
    float lrow[2] = {0.f, 0.f};

    // pcol offsets for accumulator columns 2t / 2t+1 (constant per lane)
    const int c0 = (((2 * t) & 3) << 1) | ((2 * t) >> 2);
    const int c1 = (((2 * t + 1) & 3) << 1) | ((2 * t + 1) >> 2);
    const unsigned int pb0 = w * 1152 + g * KSTR;
    const unsigned int pb1 = pb0 + 8 * KSTR;

    for (int kti = 0; kti < NSEQ / 64; kti++) {
        const int kcol0 = kti << 6;
        __syncthreads();   // previous consumers done (also covers Qs reads, iter 0)

        // ---- K: rows-of-2 mapping; columns permuted by pcol ----
        for (int e = tid; e < 1024; e += 256) {
            const int row = e >> 4, d4 = (e & 15) << 2;
            const int kb = (d4 & ~7) + ((d4 & 4) ? 1 : 0);
            float4 kv = *(const float4*)&Kg[(size_t)(kcol0 + row) * DK + d4];
            Ks[row * KSTR + kb + 0] = f2tf(kv.x);
            Ks[row * KSTR + kb + 2] = f2tf(kv.y);
            Ks[row * KSTR + kb + 4] = f2tf(kv.z);
            Ks[row * KSTR + kb + 6] = f2tf(kv.w);
        }
        // ---- V: transposed to Vt[dk][pcol(key)]; 32-rows-per-warp mapping ----
        for (int e = tid; e < 1024; e += 256) {
            const int row = e & 63;               // key
            const int d4 = (e >> 6) << 2;         // dk group
            const int pr = (row & ~7) | (((row & 3) << 1) | ((row >> 2) & 1));
            float4 vv = *(const float4*)&Vg[(size_t)(kcol0 + row) * DK + d4];
            Vt[(d4 + 0) * KSTR + pr] = f2tf(vv.x);
            Vt[(d4 + 1) * KSTR + pr] = f2tf(vv.y);
            Vt[(d4 + 2) * KSTR + pr] = f2tf(vv.z);
            Vt[(d4 + 3) * KSTR + pr] = f2tf(vv.w);
        }
        const uint4* Mg4 = (const uint4*)(g_mask8 +
            ((size_t)b * NSEQ + qrow0) * NSEQ + kcol0);
        for (int e = tid; e < 512; e += 256) {
            const int row = e >> 2, q = e & 3;
            ((uint4*)Ms)[row * 4 + q] = Mg4[(size_t)row * (NSEQ / 16) + q];
        }
        __syncthreads();

        // ---- S = Q @ K^T : one lds.64 per B-fragment ----
        float Sa[8][4] = {};
#pragma unroll
        for (int kt = 0; kt < 8; kt++) {
#pragma unroll
            for (int nt = 0; nt < 8; nt++) {
                uint2 bb = *(const uint2*)&Ks[(nt * 8 + g) * KSTR + kt * 8 + 2 * t];
                mma_tf32(Sa[nt], qf[kt], bb.x, bb.y);
            }
        }

        // ---- mask + online softmax (accumulator layout unchanged) ----
        unsigned int mbits = 0;
        float rmax0 = -1e30f, rmax1 = -1e30f;
#pragma unroll
        for (int nt = 0; nt < 8; nt++) {
            const int c = nt * 8 + 2 * t;
            uchar2 m0 = *(const uchar2*)&Ms[r0 * 64 + c];
            uchar2 m1 = *(const uchar2*)&Ms[(r0 + 8) * 64 + c];
            Sa[nt][0] = m0.x ? Sa[nt][0] * 0.125f : -1e30f;
            Sa[nt][1] = m0.y ? Sa[nt][1] * 0.125f : -1e30f;
            Sa[nt][2] = m1.x ? Sa[nt][2] * 0.125f : -1e30f;
            Sa[nt][3] = m1.y ? Sa[nt][3] * 0.125f : -1e30f;
            mbits |= (m0.x ? 1u : 0u) << (nt * 4 + 0);
            mbits |= (m0.y ? 1u : 0u) << (nt * 4 + 1);
            mbits |= (m1.x ? 1u : 0u) << (nt * 4 + 2);
            mbits |= (m1.y ? 1u : 0u) << (nt * 4 + 3);
            rmax0 = fmaxf(rmax0, fmaxf(Sa[nt][0], Sa[nt][1]));
            rmax1 = fmaxf(rmax1, fmaxf(Sa[nt][2], Sa[nt][3]));
        }
        rmax0 = fmaxf(rmax0, __shfl_xor_sync(0xffffffffu, rmax0, 1));
        rmax0 = fmaxf(rmax0, __shfl_xor_sync(0xffffffffu, rmax0, 2));
        rmax1 = fmaxf(rmax1, __shfl_xor_sync(0xffffffffu, rmax1, 1));
        rmax1 = fmaxf(rmax1, __shfl_xor_sync(0xffffffffu, rmax1, 2));

        const float mnew0 = fmaxf(mrow[0], rmax0);
        const float mnew1 = fmaxf(mrow[1], rmax1);
        const float alpha0 = __expf(mrow[0] - mnew0);
        const float alpha1 = __expf(mrow[1] - mnew1);
        mrow[0] = mnew0; mrow[1] = mnew1;

        float rsum0 = 0.f, rsum1 = 0.f;
#pragma unroll
        for (int nt = 0; nt < 8; nt++) {
            const float p0 = ((mbits >> (nt * 4 + 0)) & 1u) ? __expf(Sa[nt][0] - mnew0) : 0.f;
            const float p1 = ((mbits >> (nt * 4 + 1)) & 1u) ? __expf(Sa[nt][1] - mnew0) : 0.f;
            const float p2 = ((mbits >> (nt * 4 + 2)) & 1u) ? __expf(Sa[nt][2] - mnew1) : 0.f;
            const float p3 = ((mbits >> (nt * 4 + 3)) & 1u) ? __expf(Sa[nt][3] - mnew1) : 0.f;
            rsum0 += p0 + p1; rsum1 += p2 + p3;
            Psm[pb0 + nt * 8 + c0] = f2tf(p0);
            Psm[pb0 + nt * 8 + c1] = f2tf(p1);
            Psm[pb1 + nt * 8 + c0] = f2tf(p2);
            Psm[pb1 + nt * 8 + c1] = f2tf(p3);
            Oa[nt][0] *= alpha0; Oa[nt][1] *= alpha0;
            Oa[nt][2] *= alpha1; Oa[nt][3] *= alpha1;
        }
        rsum0 += __shfl_xor_sync(0xffffffffu, rsum0, 1);
        rsum0 += __shfl_xor_sync(0xffffffffu, rsum0, 2);
        rsum1 += __shfl_xor_sync(0xffffffffu, rsum1, 1);
        rsum1 += __shfl_xor_sync(0xffffffffu, rsum1, 2);
        lrow[0] = lrow[0] * alpha0 + rsum0;
        lrow[1] = lrow[1] * alpha1 + rsum1;

        __syncwarp();   // Psm stores visible within the warp

        // ---- O += P @ V : lds.64 for A and B fragments ----
#pragma unroll
        for (int kt = 0; kt < 8; kt++) {
            uint2 a02 = *(const uint2*)&Psm[pb0 + kt * 8 + 2 * t];
            uint2 a13 = *(const uint2*)&Psm[pb1 + kt * 8 + 2 * t];
            unsigned int a[4];
            a[0] = a02.x; a[1] = a13.x; a[2] = a02.y; a[3] = a13.y;
#pragma unroll
            for (int nt = 0; nt < 8; nt++) {
                uint2 bb = *(const uint2*)&Vt[(nt * 8 + g) * KSTR + kt * 8 + 2 * t];
                mma_tf32(Oa[nt], a, bb.x, bb.y);
            }
        }
    }

    // ---- epilogue ----
    const float inv0 = 1.f / lrow[0];
    const float inv1 = 1.f / lrow[1];
    const int grow = qrow0 + r0;
#pragma unroll
    for (int nt = 0; nt < 8; nt++) {
        const int c = h * 64 + nt * 8 + 2 * t;
        *(float2*)&g_att[((size_t)b * NSEQ + grow) * DMODEL + c] =
            make_float2(Oa[nt][0] * inv0, Oa[nt][1] * inv0);
        *(float2*)&g_att[((size_t)b * NSEQ + grow + 8) * DMODEL + c] =
            make_float2(Oa[nt][2] * inv1, Oa[nt][3] * inv1);
    }
}

// ---------------------------------------------------------------------------
// Kernel 3: output projection via tf32 mma + bias + LeakyReLU.
// ---------------------------------------------------------------------------
__global__ __launch_bounds__(256, 2) void out_mma_kernel(
    const float* __restrict__ Bm, const float* __restrict__ bias,
    float* __restrict__ out)
{
    GEMM_BODY((const float*)g_att, DMODEL, DMODEL, DMODEL)

    const int r0 = w * 16 + g;
#pragma unroll
    for (int nt = 0; nt < 8; nt++) {
        const int c = n0 + nt * 8 + 2 * t;
        const float b0 = bias[c], b1 = bias[c + 1];
#pragma unroll
        for (int half = 0; half < 2; half++) {
            const int m = m0 + r0 + half * 8;
            float v0 = acc[nt][half * 2] + b0;
            float v1 = acc[nt][half * 2 + 1] + b1;
            v0 = (v0 >= 0.f) ? v0 : 0.1f * v0;
            v1 = (v1 >= 0.f) ? v1 : 0.1f * v1;
            *(float2*)&out[(size_t)m * DMODEL + c] = make_float2(v0, v1);
        }
    }
}

// ---------------------------------------------------------------------------
extern "C" void kernel_launch(void* const* d_in, const int* in_sizes, int n_in,
                              void* d_out, int out_size)
{
    const float* x = nullptr;
    const void* mask = nullptr;
    const float* Wqkv = nullptr;
    const float* Wout = nullptr;
    const float* bout = nullptr;
    for (int i = 0; i < n_in; i++) {
        switch (in_sizes[i]) {
            case 4194304:  x    = (const float*)d_in[i]; break;
            case 16777216: mask = d_in[i];               break;
            case 786432:   Wqkv = (const float*)d_in[i]; break;
            case 262144:   Wout = (const float*)d_in[i]; break;
            case 512:      bout = (const float*)d_in[i]; break;
        }
    }
    float* out = (float*)d_out;

    cudaFuncSetAttribute(attn_mma_kernel,
                         cudaFuncAttributeMaxDynamicSharedMemorySize, 81920);

    mask_detect_kernel<<<1, 256>>>((const unsigned int*)mask);
    mask_convert_kernel<<<(unsigned)((MASK_ELEMS + 255) / 256), 256>>>(mask);
    qkv_mma_kernel<<<dim3(THREE_D / 64, M_ROWS / 128), 256>>>(x, Wqkv);
    attn_mma_kernel<<<dim3(NSEQ / 128, BH), 256, 81920>>>();
    out_mma_kernel<<<dim3(DMODEL / 64, M_ROWS / 128), 256>>>(Wout, bout, out);
}

// round 10
// speedup vs baseline: 2.7053x; 1.1583x over previous
#include <cuda_runtime.h>
#include <cstdint>

#define BSZ 4
#define NSEQ 2048
#define DMODEL 512
#define NHEAD 8
#define DK 64
#define BH (BSZ * NHEAD)          // 32
#define M_ROWS (BSZ * NSEQ)       // 8192
#define THREE_D (3 * DMODEL)      // 1536
#define MASK_ELEMS ((size_t)BSZ * NSEQ * NSEQ)   // 16,777,216

// Scratch
__device__ float g_qkv[(size_t)3 * BH * NSEQ * DK];     // ~50 MB (tf32-rounded)
__device__ float g_att[(size_t)BSZ * NSEQ * DMODEL];    // ~17 MB
__device__ unsigned char g_mask8[MASK_ELEMS];           // 16 MB
__device__ int g_mask_mode;                             // 0=u8, 1=i32, 2=f32

// ---------------------------------------------------------------------------
// helpers
// ---------------------------------------------------------------------------
__device__ __forceinline__ unsigned int f2tf(float f) {
    unsigned int u;
    asm("cvt.rna.tf32.f32 %0, %1;" : "=r"(u) : "f"(f));
    return u;
}

__device__ __forceinline__ void mma_tf32(float* c, const unsigned int* a,
                                         unsigned int b0, unsigned int b1) {
    asm volatile(
        "mma.sync.aligned.m16n8k8.row.col.f32.tf32.tf32.f32 "
        "{%0,%1,%2,%3}, {%4,%5,%6,%7}, {%8,%9}, {%0,%1,%2,%3};"
        : "+f"(c[0]), "+f"(c[1]), "+f"(c[2]), "+f"(c[3])
        : "r"(a[0]), "r"(a[1]), "r"(a[2]), "r"(a[3]), "r"(b0), "r"(b1));
}

__device__ __forceinline__ void cp16(void* smem_dst, const void* gsrc) {
    unsigned int saddr = (unsigned int)__cvta_generic_to_shared(smem_dst);
    asm volatile("cp.async.ca.shared.global [%0], [%1], 16;"
                 :: "r"(saddr), "l"(gsrc));
}
#define CP_COMMIT() asm volatile("cp.async.commit_group;" ::: "memory")
#define CP_WAIT0()  asm volatile("cp.async.wait_group 0;" ::: "memory")

// ---------------------------------------------------------------------------
// Kernel 0a/0b: mask dtype detect + normalize to uint8
// ---------------------------------------------------------------------------
__global__ void mask_detect_kernel(const unsigned int* __restrict__ m)
{
    __shared__ int sawBig, sawFloatOne;
    if (threadIdx.x == 0) { sawBig = 0; sawFloatOne = 0; }
    __syncthreads();
    for (int i = threadIdx.x; i < 16384; i += blockDim.x) {
        unsigned int w = m[i];
        if (w == 0x3F800000u) atomicOr(&sawFloatOne, 1);
        else if (w > 1u) atomicOr(&sawBig, 1);
    }
    __syncthreads();
    if (threadIdx.x == 0)
        g_mask_mode = sawFloatOne ? 2 : (sawBig ? 0 : 1);
}

__global__ __launch_bounds__(256) void mask_convert_kernel(const void* __restrict__ m)
{
    const size_t i = (size_t)blockIdx.x * blockDim.x + threadIdx.x;
    if (i >= MASK_ELEMS) return;
    const int mode = g_mask_mode;
    unsigned char v;
    if (mode == 0)      v = ((const unsigned char*)m)[i] != 0;
    else if (mode == 1) v = ((const int*)m)[i] != 0;
    else                v = ((const float*)m)[i] != 0.0f;
    g_mask8[i] = v;
}

// ---------------------------------------------------------------------------
// TF32 MMA GEMM core (unchanged from round 7)
// ---------------------------------------------------------------------------
#define GEMM_BODY(AEXPR, LDA, LDB, KDIM)                                       \
    const float* __restrict__ A = (AEXPR);                                     \
    __shared__ unsigned int As[2][128][20];                                    \
    __shared__ unsigned int Bs[2][16][68];                                     \
    const int tid = threadIdx.x;                                               \
    const int w = tid >> 5, lane = tid & 31;                                   \
    const int g = lane >> 2, t = lane & 3;                                     \
    const int n0 = blockIdx.x << 6, m0 = blockIdx.y << 7;                      \
    const int ar = tid >> 2, ak4 = (tid & 3) << 2;                             \
    const int bk = tid >> 4, bn4 = (tid & 15) << 2;                            \
    float acc[8][4] = {};                                                      \
    float4 pa0, pa1, pb0;                                                      \
    pa0 = *(const float4*)&A[(size_t)(m0 + ar) * LDA + ak4];                   \
    pa1 = *(const float4*)&A[(size_t)(m0 + ar + 64) * LDA + ak4];              \
    pb0 = *(const float4*)&Bm[(size_t)bk * LDB + n0 + bn4];                    \
    {                                                                          \
        unsigned int* a0 = &As[0][ar][ak4];                                    \
        a0[0] = f2tf(pa0.x); a0[1] = f2tf(pa0.y);                              \
        a0[2] = f2tf(pa0.z); a0[3] = f2tf(pa0.w);                              \
        unsigned int* a1 = &As[0][ar + 64][ak4];                               \
        a1[0] = f2tf(pa1.x); a1[1] = f2tf(pa1.y);                              \
        a1[2] = f2tf(pa1.z); a1[3] = f2tf(pa1.w);                              \
        unsigned int* b0p = &Bs[0][bk][bn4];                                   \
        b0p[0] = f2tf(pb0.x); b0p[1] = f2tf(pb0.y);                            \
        b0p[2] = f2tf(pb0.z); b0p[3] = f2tf(pb0.w);                            \
    }                                                                          \
    __syncthreads();                                                           \
    const int NS = (KDIM) / 16;                                                \
    for (int s = 0; s < NS; s++) {                                             \
        const int cur = s & 1;                                                 \
        if (s + 1 < NS) {                                                      \
            const int k0 = (s + 1) << 4;                                       \
            pa0 = *(const float4*)&A[(size_t)(m0 + ar) * LDA + k0 + ak4];      \
            pa1 = *(const float4*)&A[(size_t)(m0 + ar + 64) * LDA + k0 + ak4]; \
            pb0 = *(const float4*)&Bm[(size_t)(k0 + bk) * LDB + n0 + bn4];     \
        }                                                                      \
        _Pragma("unroll")                                                      \
        for (int kt = 0; kt < 2; kt++) {                                       \
            unsigned int a[4];                                                 \
            a[0] = As[cur][w * 16 + g][kt * 8 + t];                            \
            a[1] = As[cur][w * 16 + g + 8][kt * 8 + t];                        \
            a[2] = As[cur][w * 16 + g][kt * 8 + t + 4];                        \
            a[3] = As[cur][w * 16 + g + 8][kt * 8 + t + 4];                    \
            _Pragma("unroll")                                                  \
            for (int nt = 0; nt < 8; nt++) {                                   \
                unsigned int b0 = Bs[cur][kt * 8 + t][nt * 8 + g];             \
                unsigned int b1 = Bs[cur][kt * 8 + t + 4][nt * 8 + g];         \
                mma_tf32(acc[nt], a, b0, b1);                                  \
            }                                                                  \
        }                                                                      \
        if (s + 1 < NS) {                                                      \
            const int nxt = cur ^ 1;                                           \
            unsigned int* a0 = &As[nxt][ar][ak4];                              \
            a0[0] = f2tf(pa0.x); a0[1] = f2tf(pa0.y);                          \
            a0[2] = f2tf(pa0.z); a0[3] = f2tf(pa0.w);                          \
            unsigned int* a1 = &As[nxt][ar + 64][ak4];                         \
            a1[0] = f2tf(pa1.x); a1[1] = f2tf(pa1.y);                          \
            a1[2] = f2tf(pa1.z); a1[3] = f2tf(pa1.w);                          \
            unsigned int* b0p = &Bs[nxt][bk][bn4];                             \
            b0p[0] = f2tf(pb0.x); b0p[1] = f2tf(pb0.y);                        \
            b0p[2] = f2tf(pb0.z); b0p[3] = f2tf(pb0.w);                        \
        }                                                                      \
        __syncthreads();                                                       \
    }

// ---------------------------------------------------------------------------
// Kernel 1: QKV projection; epilogue rounds ALL outputs to tf32 before store
// (identical numerics to per-use cvt in attn, which is now skipped).
// ---------------------------------------------------------------------------
__global__ __launch_bounds__(256, 2) void qkv_mma_kernel(
    const float* __restrict__ X, const float* __restrict__ Bm)
{
    GEMM_BODY(X, DMODEL, THREE_D, DMODEL)

    const int r0 = w * 16 + g;
#pragma unroll
    for (int nt = 0; nt < 8; nt++) {
        const int c = n0 + nt * 8 + 2 * t;
        const int which = c >> 9;
        const int dd = c & 511;
        const int h = dd >> 6;
        const int dk = dd & 63;
#pragma unroll
        for (int half = 0; half < 2; half++) {
            const int m = m0 + r0 + half * 8;
            const int b = m >> 11;
            const int n = m & (NSEQ - 1);
            float v0 = __uint_as_float(f2tf(acc[nt][half * 2]));
            float v1 = __uint_as_float(f2tf(acc[nt][half * 2 + 1]));
            *(float2*)&g_qkv[((((size_t)which * BSZ + b) * NHEAD + h) * NSEQ + n)
                             * DK + dk] = make_float2(v0, v1);
        }
    }
}

// ---------------------------------------------------------------------------
// Kernel 2: flash attention. cp.async double-buffered K/V/mask (pre-rounded
// tf32 bits in global), ONE syncthreads per tile, shuffle-based P relayout
// (no Psm smem round trip).
// smem u32 layout: Kb0@0(4352) Kb1@4352 Vb0@8704(4608) Vb1@13312
//                  Mb0@17920(2048) Mb1@19968  -> 22016 u32 = 88064 B
// Qs (128x68, pre-loop only) overlaps Kb0+Kb1.
// ---------------------------------------------------------------------------
__global__ __launch_bounds__(256, 2) void attn_mma_kernel()
{
    extern __shared__ unsigned int smbuf[];
    float* Qs = (float*)smbuf;

    const int tid  = threadIdx.x;
    const int w    = tid >> 5;
    const int lane = tid & 31;
    const int g    = lane >> 2;
    const int t    = lane & 3;
    const int qrow0 = blockIdx.x << 7;
    const int bh = blockIdx.y;
    const int b = bh >> 3, h = bh & 7;

    const float* Qg = g_qkv + (size_t)bh * NSEQ * DK;
    const float* Kg = g_qkv + (size_t)(BH + bh) * NSEQ * DK;
    const float* Vg = g_qkv + (size_t)(2 * BH + bh) * NSEQ * DK;

    // ---- stage Q tile (raw, already tf32-rounded), extract fragments ----
    for (int e = tid; e < 2048; e += 256) {
        const int row = e >> 4, d4 = (e & 15) << 2;
        float4 v = *(const float4*)&Qg[(size_t)(qrow0 + row) * DK + d4];
        Qs[row * 68 + d4 + 0] = v.x; Qs[row * 68 + d4 + 1] = v.y;
        Qs[row * 68 + d4 + 2] = v.z; Qs[row * 68 + d4 + 3] = v.w;
    }
    __syncthreads();

    const int r0 = w * 16 + g;
    unsigned int qf[8][4];
#pragma unroll
    for (int kt = 0; kt < 8; kt++) {
        qf[kt][0] = __float_as_uint(Qs[r0 * 68 + kt * 8 + t]);
        qf[kt][1] = __float_as_uint(Qs[(r0 + 8) * 68 + kt * 8 + t]);
        qf[kt][2] = __float_as_uint(Qs[r0 * 68 + kt * 8 + t + 4]);
        qf[kt][3] = __float_as_uint(Qs[(r0 + 8) * 68 + kt * 8 + t + 4]);
    }
    __syncthreads();   // all qf read before cp.async overwrites Qs region

    float Oa[8][4] = {};
    float mrow[2] = {-1e30f, -1e30f};
    float lrow[2] = {0.f, 0.f};

    const unsigned char* Mgb = g_mask8 + ((size_t)b * NSEQ + qrow0) * NSEQ;

    // ---- prefetch tile 0 into buffer 0 ----
    {
        unsigned int* Kb = smbuf;
        unsigned int* Vb = smbuf + 8704;
        unsigned char* Mb = (unsigned char*)(smbuf + 17920);
#pragma unroll
        for (int j = 0; j < 4; j++) {
            const int e = tid + j * 256;
            const int row = e >> 4, c4 = (e & 15) << 2;
            cp16(&Kb[row * 68 + c4], &Kg[(size_t)row * DK + c4]);
            cp16(&Vb[row * 72 + c4], &Vg[(size_t)row * DK + c4]);
        }
#pragma unroll
        for (int j = 0; j < 2; j++) {
            const int e = tid + j * 256;
            const int row = e >> 2, q = e & 3;
            cp16(&Mb[row * 64 + q * 16], &Mgb[(size_t)row * NSEQ + q * 16]);
        }
        CP_COMMIT();
    }

    for (int kti = 0; kti < NSEQ / 64; kti++) {
        const int cur = kti & 1;
        CP_WAIT0();
        __syncthreads();   // tile kti ready everywhere; prev consumers done

        // ---- prefetch tile kti+1 into the other buffer ----
        if (kti + 1 < NSEQ / 64) {
            const int nxt = cur ^ 1;
            const int kc = (kti + 1) << 6;
            unsigned int* Kb = smbuf + nxt * 4352;
            unsigned int* Vb = smbuf + 8704 + nxt * 4608;
            unsigned char* Mb = (unsigned char*)(smbuf + 17920 + nxt * 2048);
#pragma unroll
            for (int j = 0; j < 4; j++) {
                const int e = tid + j * 256;
                const int row = e >> 4, c4 = (e & 15) << 2;
                cp16(&Kb[row * 68 + c4], &Kg[(size_t)(kc + row) * DK + c4]);
                cp16(&Vb[row * 72 + c4], &Vg[(size_t)(kc + row) * DK + c4]);
            }
#pragma unroll
            for (int j = 0; j < 2; j++) {
                const int e = tid + j * 256;
                const int row = e >> 2, q = e & 3;
                cp16(&Mb[row * 64 + q * 16],
                     &Mgb[(size_t)row * NSEQ + kc + q * 16]);
            }
            CP_COMMIT();
        }

        const unsigned int* Ks = smbuf + cur * 4352;
        const unsigned int* Vs = smbuf + 8704 + cur * 4608;
        const unsigned char* Ms = (const unsigned char*)(smbuf + 17920 + cur * 2048);

        // ---- S = Q @ K^T (K key-major, stride 68: banks 4g+t, clean) ----
        float Sa[8][4] = {};
#pragma unroll
        for (int kt = 0; kt < 8; kt++) {
#pragma unroll
            for (int nt = 0; nt < 8; nt++) {
                const unsigned int* kr = &Ks[(nt * 8 + g) * 68 + kt * 8 + t];
                mma_tf32(Sa[nt], qf[kt], kr[0], kr[4]);
            }
        }

        // ---- mask + online softmax; P kept in Sa registers ----
        unsigned int mbits = 0;
        float rmax0 = -1e30f, rmax1 = -1e30f;
#pragma unroll
        for (int nt = 0; nt < 8; nt++) {
            const int c = nt * 8 + 2 * t;
            uchar2 m0 = *(const uchar2*)&Ms[r0 * 64 + c];
            uchar2 m1 = *(const uchar2*)&Ms[(r0 + 8) * 64 + c];
            Sa[nt][0] = m0.x ? Sa[nt][0] * 0.125f : -1e30f;
            Sa[nt][1] = m0.y ? Sa[nt][1] * 0.125f : -1e30f;
            Sa[nt][2] = m1.x ? Sa[nt][2] * 0.125f : -1e30f;
            Sa[nt][3] = m1.y ? Sa[nt][3] * 0.125f : -1e30f;
            mbits |= (m0.x ? 1u : 0u) << (nt * 4 + 0);
            mbits |= (m0.y ? 1u : 0u) << (nt * 4 + 1);
            mbits |= (m1.x ? 1u : 0u) << (nt * 4 + 2);
            mbits |= (m1.y ? 1u : 0u) << (nt * 4 + 3);
            rmax0 = fmaxf(rmax0, fmaxf(Sa[nt][0], Sa[nt][1]));
            rmax1 = fmaxf(rmax1, fmaxf(Sa[nt][2], Sa[nt][3]));
        }
        rmax0 = fmaxf(rmax0, __shfl_xor_sync(0xffffffffu, rmax0, 1));
        rmax0 = fmaxf(rmax0, __shfl_xor_sync(0xffffffffu, rmax0, 2));
        rmax1 = fmaxf(rmax1, __shfl_xor_sync(0xffffffffu, rmax1, 1));
        rmax1 = fmaxf(rmax1, __shfl_xor_sync(0xffffffffu, rmax1, 2));

        const float mnew0 = fmaxf(mrow[0], rmax0);
        const float mnew1 = fmaxf(mrow[1], rmax1);
        const float alpha0 = __expf(mrow[0] - mnew0);
        const float alpha1 = __expf(mrow[1] - mnew1);
        mrow[0] = mnew0; mrow[1] = mnew1;

        float rsum0 = 0.f, rsum1 = 0.f;
#pragma unroll
        for (int nt = 0; nt < 8; nt++) {
            const float p0 = ((mbits >> (nt * 4 + 0)) & 1u) ? __expf(Sa[nt][0] - mnew0) : 0.f;
            const float p1 = ((mbits >> (nt * 4 + 1)) & 1u) ? __expf(Sa[nt][1] - mnew0) : 0.f;
            const float p2 = ((mbits >> (nt * 4 + 2)) & 1u) ? __expf(Sa[nt][2] - mnew1) : 0.f;
            const float p3 = ((mbits >> (nt * 4 + 3)) & 1u) ? __expf(Sa[nt][3] - mnew1) : 0.f;
            rsum0 += p0 + p1; rsum1 += p2 + p3;
            Sa[nt][0] = p0; Sa[nt][1] = p1; Sa[nt][2] = p2; Sa[nt][3] = p3;
            Oa[nt][0] *= alpha0; Oa[nt][1] *= alpha0;
            Oa[nt][2] *= alpha1; Oa[nt][3] *= alpha1;
        }
        rsum0 += __shfl_xor_sync(0xffffffffu, rsum0, 1);
        rsum0 += __shfl_xor_sync(0xffffffffu, rsum0, 2);
        rsum1 += __shfl_xor_sync(0xffffffffu, rsum1, 1);
        rsum1 += __shfl_xor_sync(0xffffffffu, rsum1, 2);
        lrow[0] = lrow[0] * alpha0 + rsum0;
        lrow[1] = lrow[1] * alpha1 + rsum1;

        // ---- O += P @ V : A-fragments built from Sa via shuffles ----
        const int s0 = (lane & ~3) | (t >> 1);
        const int s1 = s0 + 2;
        const bool odd = (t & 1);
#pragma unroll
        for (int kt = 0; kt < 8; kt++) {
            const unsigned int u0 = f2tf(Sa[kt][0]);
            const unsigned int u1 = f2tf(Sa[kt][1]);
            const unsigned int u2 = f2tf(Sa[kt][2]);
            const unsigned int u3 = f2tf(Sa[kt][3]);
            const unsigned int w00 = __shfl_sync(0xffffffffu, u0, s0);
            const unsigned int w10 = __shfl_sync(0xffffffffu, u1, s0);
            const unsigned int w20 = __shfl_sync(0xffffffffu, u2, s0);
            const unsigned int w30 = __shfl_sync(0xffffffffu, u3, s0);
            const unsigned int w01 = __shfl_sync(0xffffffffu, u0, s1);
            const unsigned int w11 = __shfl_sync(0xffffffffu, u1, s1);
            const unsigned int w21 = __shfl_sync(0xffffffffu, u2, s1);
            const unsigned int w31 = __shfl_sync(0xffffffffu, u3, s1);
            unsigned int a[4];
            a[0] = odd ? w10 : w00;   // row g,   col t
            a[1] = odd ? w30 : w20;   // row g+8, col t
            a[2] = odd ? w11 : w01;   // row g,   col t+4
            a[3] = odd ? w31 : w21;   // row g+8, col t+4
#pragma unroll
            for (int nt = 0; nt < 8; nt++) {
                const unsigned int* vr = &Vs[(kt * 8 + t) * 72 + nt * 8 + g];
                mma_tf32(Oa[nt], a, vr[0], vr[4 * 72]);
            }
        }
    }

    // ---- epilogue ----
    const float inv0 = 1.f / lrow[0];
    const float inv1 = 1.f / lrow[1];
    const int grow = qrow0 + r0;
#pragma unroll
    for (int nt = 0; nt < 8; nt++) {
        const int c = h * 64 + nt * 8 + 2 * t;
        *(float2*)&g_att[((size_t)b * NSEQ + grow) * DMODEL + c] =
            make_float2(Oa[nt][0] * inv0, Oa[nt][1] * inv0);
        *(float2*)&g_att[((size_t)b * NSEQ + grow + 8) * DMODEL + c] =
            make_float2(Oa[nt][2] * inv1, Oa[nt][3] * inv1);
    }
}

// ---------------------------------------------------------------------------
// Kernel 3: output projection via tf32 mma + bias + LeakyReLU.
// ---------------------------------------------------------------------------
__global__ __launch_bounds__(256, 2) void out_mma_kernel(
    const float* __restrict__ Bm, const float* __restrict__ bias,
    float* __restrict__ out)
{
    GEMM_BODY((const float*)g_att, DMODEL, DMODEL, DMODEL)

    const int r0 = w * 16 + g;
#pragma unroll
    for (int nt = 0; nt < 8; nt++) {
        const int c = n0 + nt * 8 + 2 * t;
        const float b0 = bias[c], b1 = bias[c + 1];
#pragma unroll
        for (int half = 0; half < 2; half++) {
            const int m = m0 + r0 + half * 8;
            float v0 = acc[nt][half * 2] + b0;
            float v1 = acc[nt][half * 2 + 1] + b1;
            v0 = (v0 >= 0.f) ? v0 : 0.1f * v0;
            v1 = (v1 >= 0.f) ? v1 : 0.1f * v1;
            *(float2*)&out[(size_t)m * DMODEL + c] = make_float2(v0, v1);
        }
    }
}

// ---------------------------------------------------------------------------
extern "C" void kernel_launch(void* const* d_in, const int* in_sizes, int n_in,
                              void* d_out, int out_size)
{
    const float* x = nullptr;
    const void* mask = nullptr;
    const float* Wqkv = nullptr;
    const float* Wout = nullptr;
    const float* bout = nullptr;
    for (int i = 0; i < n_in; i++) {
        switch (in_sizes[i]) {
            case 4194304:  x    = (const float*)d_in[i]; break;
            case 16777216: mask = d_in[i];               break;
            case 786432:   Wqkv = (const float*)d_in[i]; break;
            case 262144:   Wout = (const float*)d_in[i]; break;
            case 512:      bout = (const float*)d_in[i]; break;
        }
    }
    float* out = (float*)d_out;

    cudaFuncSetAttribute(attn_mma_kernel,
                         cudaFuncAttributeMaxDynamicSharedMemorySize, 88064);

    mask_detect_kernel<<<1, 256>>>((const unsigned int*)mask);
    mask_convert_kernel<<<(unsigned)((MASK_ELEMS + 255) / 256), 256>>>(mask);
    qkv_mma_kernel<<<dim3(THREE_D / 64, M_ROWS / 128), 256>>>(x, Wqkv);
    attn_mma_kernel<<<dim3(NSEQ / 128, BH), 256, 88064>>>();
    out_mma_kernel<<<dim3(DMODEL / 64, M_ROWS / 128), 256>>>(Wout, bout, out);
}

// round 11
// speedup vs baseline: 3.1019x; 1.1466x over previous
#include <cuda_runtime.h>
#include <cstdint>

#define BSZ 4
#define NSEQ 2048
#define DMODEL 512
#define NHEAD 8
#define DK 64
#define BH (BSZ * NHEAD)          // 32
#define M_ROWS (BSZ * NSEQ)       // 8192
#define THREE_D (3 * DMODEL)      // 1536
#define MASK_ELEMS ((size_t)BSZ * NSEQ * NSEQ)   // 16,777,216

// Scratch
__device__ float g_qkv[(size_t)3 * BH * NSEQ * DK];     // ~50 MB (tf32-rounded)
__device__ float g_att[(size_t)BSZ * NSEQ * DMODEL];    // ~17 MB (tf32-rounded)
__device__ unsigned char g_mask8[MASK_ELEMS];           // 16 MB
__device__ int g_mask_mode;
__device__ float g_xr[(size_t)M_ROWS * DMODEL];         // 16.8 MB tf32-rounded X
__device__ float g_wqkvr[(size_t)DMODEL * THREE_D];     // 3.1 MB
__device__ float g_woutr[(size_t)DMODEL * DMODEL];      // 1 MB

// ---------------------------------------------------------------------------
// helpers
// ---------------------------------------------------------------------------
__device__ __forceinline__ unsigned int f2tf(float f) {
    unsigned int u;
    asm("cvt.rna.tf32.f32 %0, %1;" : "=r"(u) : "f"(f));
    return u;
}
__device__ __forceinline__ float tfr(float f) { return __uint_as_float(f2tf(f)); }

__device__ __forceinline__ void mma_tf32(float* c, const unsigned int* a,
                                         unsigned int b0, unsigned int b1) {
    asm volatile(
        "mma.sync.aligned.m16n8k8.row.col.f32.tf32.tf32.f32 "
        "{%0,%1,%2,%3}, {%4,%5,%6,%7}, {%8,%9}, {%0,%1,%2,%3};"
        : "+f"(c[0]), "+f"(c[1]), "+f"(c[2]), "+f"(c[3])
        : "r"(a[0]), "r"(a[1]), "r"(a[2]), "r"(a[3]), "r"(b0), "r"(b1));
}

__device__ __forceinline__ void cp16(void* smem_dst, const void* gsrc) {
    unsigned int saddr = (unsigned int)__cvta_generic_to_shared(smem_dst);
    asm volatile("cp.async.ca.shared.global [%0], [%1], 16;"
                 :: "r"(saddr), "l"(gsrc));
}
#define CP_COMMIT() asm volatile("cp.async.commit_group;" ::: "memory")
#define CP_WAIT0()  asm volatile("cp.async.wait_group 0;" ::: "memory")

// ---------------------------------------------------------------------------
// Kernel 0: mask dtype detect + normalize; pre-round X/W to tf32
// ---------------------------------------------------------------------------
__global__ void mask_detect_kernel(const unsigned int* __restrict__ m)
{
    __shared__ int sawBig, sawFloatOne;
    if (threadIdx.x == 0) { sawBig = 0; sawFloatOne = 0; }
    __syncthreads();
    for (int i = threadIdx.x; i < 16384; i += blockDim.x) {
        unsigned int w = m[i];
        if (w == 0x3F800000u) atomicOr(&sawFloatOne, 1);
        else if (w > 1u) atomicOr(&sawBig, 1);
    }
    __syncthreads();
    if (threadIdx.x == 0)
        g_mask_mode = sawFloatOne ? 2 : (sawBig ? 0 : 1);
}

__global__ __launch_bounds__(256) void mask_convert_kernel(const void* __restrict__ m)
{
    const size_t i = (size_t)blockIdx.x * blockDim.x + threadIdx.x;
    if (i >= MASK_ELEMS) return;
    const int mode = g_mask_mode;
    unsigned char v;
    if (mode == 0)      v = ((const unsigned char*)m)[i] != 0;
    else if (mode == 1) v = ((const int*)m)[i] != 0;
    else                v = ((const float*)m)[i] != 0.0f;
    g_mask8[i] = v;
}

__global__ __launch_bounds__(256) void preround_kernel(
    const float* __restrict__ x, const float* __restrict__ wqkv,
    const float* __restrict__ wout)
{
    const size_t i = ((size_t)blockIdx.x * blockDim.x + threadIdx.x) * 4;
    if (i < (size_t)M_ROWS * DMODEL) {
        float4 v = *(const float4*)&x[i];
        *(float4*)&g_xr[i] = make_float4(tfr(v.x), tfr(v.y), tfr(v.z), tfr(v.w));
    }
    if (i < (size_t)DMODEL * THREE_D) {
        float4 v = *(const float4*)&wqkv[i];
        *(float4*)&g_wqkvr[i] = make_float4(tfr(v.x), tfr(v.y), tfr(v.z), tfr(v.w));
    }
    if (i < (size_t)DMODEL * DMODEL) {
        float4 v = *(const float4*)&wout[i];
        *(float4*)&g_woutr[i] = make_float4(tfr(v.x), tfr(v.y), tfr(v.z), tfr(v.w));
    }
}

// ---------------------------------------------------------------------------
// TF32 MMA GEMM core v2: 128x128 block tile, BK=16, warps 4m x 2n, each
// m32 x n64. cp.async double-buffered staging (inputs pre-rounded; no cvt).
// As[m][20]: frag banks (20g+t)%32 distinct; row 80B (16B-mult) for cp16.
// Bs[k][136]: frag banks (8t+g)%32 distinct; row 544B for cp16.
// ---------------------------------------------------------------------------
#define GEMM_BODY2(AEXPR, BEXPR, LDA, LDB, KDIM)                               \
    const float* __restrict__ A = (AEXPR);                                     \
    const float* __restrict__ Bm = (BEXPR);                                    \
    __shared__ unsigned int As[2][128][20];                                    \
    __shared__ unsigned int Bs[2][16][136];                                    \
    const int tid = threadIdx.x;                                               \
    const int w = tid >> 5, lane = tid & 31;                                   \
    const int g = lane >> 2, t = lane & 3;                                     \
    const int n0 = blockIdx.x << 7, m0 = blockIdx.y << 7;                      \
    const int wm = (w & 3) << 5, wn = (w >> 2) << 6;                           \
    const int arow = tid >> 1, ac4 = (tid & 1) << 3;  /* 2x cp16 A rows */     \
    const int brow = tid >> 4, bn4 = (tid & 15) << 3; /* 2x cp16 B rows */     \
    float acc[2][8][4] = {};                                                   \
    {                                                                          \
        cp16(&As[0][arow][ac4], &A[(size_t)(m0 + arow) * LDA + ac4]);          \
        cp16(&As[0][arow][ac4 + 4], &A[(size_t)(m0 + arow) * LDA + ac4 + 4]);  \
        cp16(&Bs[0][brow][bn4], &Bm[(size_t)brow * LDB + n0 + bn4]);           \
        cp16(&Bs[0][brow][bn4 + 4], &Bm[(size_t)brow * LDB + n0 + bn4 + 4]);   \
        CP_COMMIT();                                                           \
    }                                                                          \
    const int NS = (KDIM) / 16;                                                \
    for (int s = 0; s < NS; s++) {                                             \
        const int cur = s & 1;                                                 \
        CP_WAIT0();                                                            \
        __syncthreads();                                                       \
        if (s + 1 < NS) {                                                      \
            const int nxt = cur ^ 1;                                           \
            const int k0 = (s + 1) << 4;                                       \
            cp16(&As[nxt][arow][ac4],                                          \
                 &A[(size_t)(m0 + arow) * LDA + k0 + ac4]);                    \
            cp16(&As[nxt][arow][ac4 + 4],                                      \
                 &A[(size_t)(m0 + arow) * LDA + k0 + ac4 + 4]);                \
            cp16(&Bs[nxt][brow][bn4],                                          \
                 &Bm[(size_t)(k0 + brow) * LDB + n0 + bn4]);                   \
            cp16(&Bs[nxt][brow][bn4 + 4],                                      \
                 &Bm[(size_t)(k0 + brow) * LDB + n0 + bn4 + 4]);               \
            CP_COMMIT();                                                       \
        }                                                                      \
        _Pragma("unroll")                                                      \
        for (int kt = 0; kt < 2; kt++) {                                       \
            unsigned int a0[4], a1[4];                                         \
            a0[0] = As[cur][wm + g][kt * 8 + t];                               \
            a0[1] = As[cur][wm + g + 8][kt * 8 + t];                           \
            a0[2] = As[cur][wm + g][kt * 8 + t + 4];                           \
            a0[3] = As[cur][wm + g + 8][kt * 8 + t + 4];                       \
            a1[0] = As[cur][wm + 16 + g][kt * 8 + t];                          \
            a1[1] = As[cur][wm + 24 + g][kt * 8 + t];                          \
            a1[2] = As[cur][wm + 16 + g][kt * 8 + t + 4];                      \
            a1[3] = As[cur][wm + 24 + g][kt * 8 + t + 4];                      \
            _Pragma("unroll")                                                  \
            for (int nt = 0; nt < 8; nt++) {                                   \
                unsigned int b0 = Bs[cur][kt * 8 + t][wn + nt * 8 + g];        \
                unsigned int b1 = Bs[cur][kt * 8 + t + 4][wn + nt * 8 + g];    \
                mma_tf32(acc[0][nt], a0, b0, b1);                              \
                mma_tf32(acc[1][nt], a1, b0, b1);                              \
            }                                                                  \
        }                                                                      \
    }

// ---------------------------------------------------------------------------
// Kernel 1: QKV projection (v2 core), epilogue rounds to tf32 + scatters.
// ---------------------------------------------------------------------------
__global__ __launch_bounds__(256, 2) void qkv_mma_kernel()
{
    GEMM_BODY2((const float*)g_xr, (const float*)g_wqkvr, DMODEL, THREE_D, DMODEL)

#pragma unroll
    for (int nt = 0; nt < 8; nt++) {
        const int c = n0 + wn + nt * 8 + 2 * t;
        const int which = c >> 9;
        const int dd = c & 511;
        const int h = dd >> 6;
        const int dk = dd & 63;
        float* base = g_qkv + (((size_t)which * BSZ) * NHEAD + h) * NSEQ * DK + dk;
#pragma unroll
        for (int mh = 0; mh < 2; mh++) {
#pragma unroll
            for (int half = 0; half < 2; half++) {
                const int m = m0 + wm + mh * 16 + g + half * 8;
                const int b = m >> 11;
                const int n = m & (NSEQ - 1);
                *(float2*)&base[((size_t)b * NHEAD * NSEQ + n) * DK] =
                    make_float2(tfr(acc[mh][nt][half * 2]),
                                tfr(acc[mh][nt][half * 2 + 1]));
            }
        }
    }
}

// ---------------------------------------------------------------------------
// Kernel 2: flash attention (unchanged from round 10 except epilogue rounds
// g_att to tf32 so out_mma needs no cvt — bit-identical to prior staging cvt).
// ---------------------------------------------------------------------------
__global__ __launch_bounds__(256, 2) void attn_mma_kernel()
{
    extern __shared__ unsigned int smbuf[];
    float* Qs = (float*)smbuf;

    const int tid  = threadIdx.x;
    const int w    = tid >> 5;
    const int lane = tid & 31;
    const int g    = lane >> 2;
    const int t    = lane & 3;
    const int qrow0 = blockIdx.x << 7;
    const int bh = blockIdx.y;
    const int b = bh >> 3, h = bh & 7;

    const float* Qg = g_qkv + (size_t)bh * NSEQ * DK;
    const float* Kg = g_qkv + (size_t)(BH + bh) * NSEQ * DK;
    const float* Vg = g_qkv + (size_t)(2 * BH + bh) * NSEQ * DK;

    for (int e = tid; e < 2048; e += 256) {
        const int row = e >> 4, d4 = (e & 15) << 2;
        float4 v = *(const float4*)&Qg[(size_t)(qrow0 + row) * DK + d4];
        Qs[row * 68 + d4 + 0] = v.x; Qs[row * 68 + d4 + 1] = v.y;
        Qs[row * 68 + d4 + 2] = v.z; Qs[row * 68 + d4 + 3] = v.w;
    }
    __syncthreads();

    const int r0 = w * 16 + g;
    unsigned int qf[8][4];
#pragma unroll
    for (int kt = 0; kt < 8; kt++) {
        qf[kt][0] = __float_as_uint(Qs[r0 * 68 + kt * 8 + t]);
        qf[kt][1] = __float_as_uint(Qs[(r0 + 8) * 68 + kt * 8 + t]);
        qf[kt][2] = __float_as_uint(Qs[r0 * 68 + kt * 8 + t + 4]);
        qf[kt][3] = __float_as_uint(Qs[(r0 + 8) * 68 + kt * 8 + t + 4]);
    }
    __syncthreads();

    float Oa[8][4] = {};
    float mrow[2] = {-1e30f, -1e30f};
    float lrow[2] = {0.f, 0.f};

    const unsigned char* Mgb = g_mask8 + ((size_t)b * NSEQ + qrow0) * NSEQ;

    {
        unsigned int* Kb = smbuf;
        unsigned int* Vb = smbuf + 8704;
        unsigned char* Mb = (unsigned char*)(smbuf + 17920);
#pragma unroll
        for (int j = 0; j < 4; j++) {
            const int e = tid + j * 256;
            const int row = e >> 4, c4 = (e & 15) << 2;
            cp16(&Kb[row * 68 + c4], &Kg[(size_t)row * DK + c4]);
            cp16(&Vb[row * 72 + c4], &Vg[(size_t)row * DK + c4]);
        }
#pragma unroll
        for (int j = 0; j < 2; j++) {
            const int e = tid + j * 256;
            const int row = e >> 2, q = e & 3;
            cp16(&Mb[row * 64 + q * 16], &Mgb[(size_t)row * NSEQ + q * 16]);
        }
        CP_COMMIT();
    }

    for (int kti = 0; kti < NSEQ / 64; kti++) {
        const int cur = kti & 1;
        CP_WAIT0();
        __syncthreads();

        if (kti + 1 < NSEQ / 64) {
            const int nxt = cur ^ 1;
            const int kc = (kti + 1) << 6;
            unsigned int* Kb = smbuf + nxt * 4352;
            unsigned int* Vb = smbuf + 8704 + nxt * 4608;
            unsigned char* Mb = (unsigned char*)(smbuf + 17920 + nxt * 2048);
#pragma unroll
            for (int j = 0; j < 4; j++) {
                const int e = tid + j * 256;
                const int row = e >> 4, c4 = (e & 15) << 2;
                cp16(&Kb[row * 68 + c4], &Kg[(size_t)(kc + row) * DK + c4]);
                cp16(&Vb[row * 72 + c4], &Vg[(size_t)(kc + row) * DK + c4]);
            }
#pragma unroll
            for (int j = 0; j < 2; j++) {
                const int e = tid + j * 256;
                const int row = e >> 2, q = e & 3;
                cp16(&Mb[row * 64 + q * 16],
                     &Mgb[(size_t)row * NSEQ + kc + q * 16]);
            }
            CP_COMMIT();
        }

        const unsigned int* Ks = smbuf + cur * 4352;
        const unsigned int* Vs = smbuf + 8704 + cur * 4608;
        const unsigned char* Ms = (const unsigned char*)(smbuf + 17920 + cur * 2048);

        float Sa[8][4] = {};
#pragma unroll
        for (int kt = 0; kt < 8; kt++) {
#pragma unroll
            for (int nt = 0; nt < 8; nt++) {
                const unsigned int* kr = &Ks[(nt * 8 + g) * 68 + kt * 8 + t];
                mma_tf32(Sa[nt], qf[kt], kr[0], kr[4]);
            }
        }

        unsigned int mbits = 0;
        float rmax0 = -1e30f, rmax1 = -1e30f;
#pragma unroll
        for (int nt = 0; nt < 8; nt++) {
            const int c = nt * 8 + 2 * t;
            uchar2 m0 = *(const uchar2*)&Ms[r0 * 64 + c];
            uchar2 m1 = *(const uchar2*)&Ms[(r0 + 8) * 64 + c];
            Sa[nt][0] = m0.x ? Sa[nt][0] * 0.125f : -1e30f;
            Sa[nt][1] = m0.y ? Sa[nt][1] * 0.125f : -1e30f;
            Sa[nt][2] = m1.x ? Sa[nt][2] * 0.125f : -1e30f;
            Sa[nt][3] = m1.y ? Sa[nt][3] * 0.125f : -1e30f;
            mbits |= (m0.x ? 1u : 0u) << (nt * 4 + 0);
            mbits |= (m0.y ? 1u : 0u) << (nt * 4 + 1);
            mbits |= (m1.x ? 1u : 0u) << (nt * 4 + 2);
            mbits |= (m1.y ? 1u : 0u) << (nt * 4 + 3);
            rmax0 = fmaxf(rmax0, fmaxf(Sa[nt][0], Sa[nt][1]));
            rmax1 = fmaxf(rmax1, fmaxf(Sa[nt][2], Sa[nt][3]));
        }
        rmax0 = fmaxf(rmax0, __shfl_xor_sync(0xffffffffu, rmax0, 1));
        rmax0 = fmaxf(rmax0, __shfl_xor_sync(0xffffffffu, rmax0, 2));
        rmax1 = fmaxf(rmax1, __shfl_xor_sync(0xffffffffu, rmax1, 1));
        rmax1 = fmaxf(rmax1, __shfl_xor_sync(0xffffffffu, rmax1, 2));

        const float mnew0 = fmaxf(mrow[0], rmax0);
        const float mnew1 = fmaxf(mrow[1], rmax1);
        const float alpha0 = __expf(mrow[0] - mnew0);
        const float alpha1 = __expf(mrow[1] - mnew1);
        mrow[0] = mnew0; mrow[1] = mnew1;

        float rsum0 = 0.f, rsum1 = 0.f;
#pragma unroll
        for (int nt = 0; nt < 8; nt++) {
            const float p0 = ((mbits >> (nt * 4 + 0)) & 1u) ? __expf(Sa[nt][0] - mnew0) : 0.f;
            const float p1 = ((mbits >> (nt * 4 + 1)) & 1u) ? __expf(Sa[nt][1] - mnew0) : 0.f;
            const float p2 = ((mbits >> (nt * 4 + 2)) & 1u) ? __expf(Sa[nt][2] - mnew1) : 0.f;
            const float p3 = ((mbits >> (nt * 4 + 3)) & 1u) ? __expf(Sa[nt][3] - mnew1) : 0.f;
            rsum0 += p0 + p1; rsum1 += p2 + p3;
            Sa[nt][0] = p0; Sa[nt][1] = p1; Sa[nt][2] = p2; Sa[nt][3] = p3;
            Oa[nt][0] *= alpha0; Oa[nt][1] *= alpha0;
            Oa[nt][2] *= alpha1; Oa[nt][3] *= alpha1;
        }
        rsum0 += __shfl_xor_sync(0xffffffffu, rsum0, 1);
        rsum0 += __shfl_xor_sync(0xffffffffu, rsum0, 2);
        rsum1 += __shfl_xor_sync(0xffffffffu, rsum1, 1);
        rsum1 += __shfl_xor_sync(0xffffffffu, rsum1, 2);
        lrow[0] = lrow[0] * alpha0 + rsum0;
        lrow[1] = lrow[1] * alpha1 + rsum1;

        const int s0 = (lane & ~3) | (t >> 1);
        const int s1 = s0 + 2;
        const bool odd = (t & 1);
#pragma unroll
        for (int kt = 0; kt < 8; kt++) {
            const unsigned int u0 = f2tf(Sa[kt][0]);
            const unsigned int u1 = f2tf(Sa[kt][1]);
            const unsigned int u2 = f2tf(Sa[kt][2]);
            const unsigned int u3 = f2tf(Sa[kt][3]);
            const unsigned int w00 = __shfl_sync(0xffffffffu, u0, s0);
            const unsigned int w10 = __shfl_sync(0xffffffffu, u1, s0);
            const unsigned int w20 = __shfl_sync(0xffffffffu, u2, s0);
            const unsigned int w30 = __shfl_sync(0xffffffffu, u3, s0);
            const unsigned int w01 = __shfl_sync(0xffffffffu, u0, s1);
            const unsigned int w11 = __shfl_sync(0xffffffffu, u1, s1);
            const unsigned int w21 = __shfl_sync(0xffffffffu, u2, s1);
            const unsigned int w31 = __shfl_sync(0xffffffffu, u3, s1);
            unsigned int a[4];
            a[0] = odd ? w10 : w00;
            a[1] = odd ? w30 : w20;
            a[2] = odd ? w11 : w01;
            a[3] = odd ? w31 : w21;
#pragma unroll
            for (int nt = 0; nt < 8; nt++) {
                const unsigned int* vr = &Vs[(kt * 8 + t) * 72 + nt * 8 + g];
                mma_tf32(Oa[nt], a, vr[0], vr[4 * 72]);
            }
        }
    }

    const float inv0 = 1.f / lrow[0];
    const float inv1 = 1.f / lrow[1];
    const int grow = qrow0 + r0;
#pragma unroll
    for (int nt = 0; nt < 8; nt++) {
        const int c = h * 64 + nt * 8 + 2 * t;
        *(float2*)&g_att[((size_t)b * NSEQ + grow) * DMODEL + c] =
            make_float2(tfr(Oa[nt][0] * inv0), tfr(Oa[nt][1] * inv0));
        *(float2*)&g_att[((size_t)b * NSEQ + grow + 8) * DMODEL + c] =
            make_float2(tfr(Oa[nt][2] * inv1), tfr(Oa[nt][3] * inv1));
    }
}

// ---------------------------------------------------------------------------
// Kernel 3: output projection (v2 core) + bias + LeakyReLU.
// ---------------------------------------------------------------------------
__global__ __launch_bounds__(256, 2) void out_mma_kernel(
    const float* __restrict__ bias, float* __restrict__ out)
{
    GEMM_BODY2((const float*)g_att, (const float*)g_woutr, DMODEL, DMODEL, DMODEL)

#pragma unroll
    for (int nt = 0; nt < 8; nt++) {
        const int c = n0 + wn + nt * 8 + 2 * t;
        const float b0 = bias[c], b1 = bias[c + 1];
#pragma unroll
        for (int mh = 0; mh < 2; mh++) {
#pragma unroll
            for (int half = 0; half < 2; half++) {
                const int m = m0 + wm + mh * 16 + g + half * 8;
                float v0 = acc[mh][nt][half * 2] + b0;
                float v1 = acc[mh][nt][half * 2 + 1] + b1;
                v0 = (v0 >= 0.f) ? v0 : 0.1f * v0;
                v1 = (v1 >= 0.f) ? v1 : 0.1f * v1;
                *(float2*)&out[(size_t)m * DMODEL + c] = make_float2(v0, v1);
            }
        }
    }
}

// ---------------------------------------------------------------------------
extern "C" void kernel_launch(void* const* d_in, const int* in_sizes, int n_in,
                              void* d_out, int out_size)
{
    const float* x = nullptr;
    const void* mask = nullptr;
    const float* Wqkv = nullptr;
    const float* Wout = nullptr;
    const float* bout = nullptr;
    for (int i = 0; i < n_in; i++) {
        switch (in_sizes[i]) {
            case 4194304:  x    = (const float*)d_in[i]; break;
            case 16777216: mask = d_in[i];               break;
            case 786432:   Wqkv = (const float*)d_in[i]; break;
            case 262144:   Wout = (const float*)d_in[i]; break;
            case 512:      bout = (const float*)d_in[i]; break;
        }
    }
    float* out = (float*)d_out;

    cudaFuncSetAttribute(attn_mma_kernel,
                         cudaFuncAttributeMaxDynamicSharedMemorySize, 88064);

    mask_detect_kernel<<<1, 256>>>((const unsigned int*)mask);
    mask_convert_kernel<<<(unsigned)((MASK_ELEMS + 255) / 256), 256>>>(mask);
    preround_kernel<<<4096, 256>>>(x, Wqkv, Wout);
    qkv_mma_kernel<<<dim3(THREE_D / 128, M_ROWS / 128), 256>>>();
    attn_mma_kernel<<<dim3(NSEQ / 128, BH), 256, 88064>>>();
    out_mma_kernel<<<dim3(DMODEL / 128, M_ROWS / 128), 256>>>(bout, out);
}

// round 13
// speedup vs baseline: 4.6525x; 1.4999x over previous
#include <cuda_runtime.h>
#include <cuda_fp16.h>
#include <cstdint>

#define BSZ 4
#define NSEQ 2048
#define DMODEL 512
#define NHEAD 8
#define DK 64
#define BH (BSZ * NHEAD)          // 32
#define M_ROWS (BSZ * NSEQ)       // 8192
#define THREE_D (3 * DMODEL)      // 1536
#define MASK_ELEMS ((size_t)BSZ * NSEQ * NSEQ)   // 16,777,216

// Scratch (all fp16 now)
__device__ __half g_q[(size_t)BH * NSEQ * DK];
__device__ __half g_k[(size_t)BH * NSEQ * DK];
__device__ __half g_vt[(size_t)BH * DK * NSEQ];          // transposed [bh][dk][key]
__device__ __half g_att[(size_t)M_ROWS * DMODEL];
__device__ __half g_xh[(size_t)M_ROWS * DMODEL];
__device__ __half2 g_wqkv2[(size_t)(DMODEL / 2) * THREE_D];  // [k/2][n] pairs
__device__ __half2 g_wout2[(size_t)(DMODEL / 2) * DMODEL];
__device__ unsigned char g_mask8[MASK_ELEMS];
__device__ int g_mask_mode;

// ---------------------------------------------------------------------------
// helpers
// ---------------------------------------------------------------------------
__device__ __forceinline__ void mma_f16(float* c, const unsigned int* a,
                                        unsigned int b0, unsigned int b1) {
    asm volatile(
        "mma.sync.aligned.m16n8k16.row.col.f32.f16.f16.f32 "
        "{%0,%1,%2,%3}, {%4,%5,%6,%7}, {%8,%9}, {%0,%1,%2,%3};"
        : "+f"(c[0]), "+f"(c[1]), "+f"(c[2]), "+f"(c[3])
        : "r"(a[0]), "r"(a[1]), "r"(a[2]), "r"(a[3]), "r"(b0), "r"(b1));
}

__device__ __forceinline__ unsigned int packh2(float lo, float hi) {
    __half2 h = __floats2half2_rn(lo, hi);
    return *(unsigned int*)&h;
}

__device__ __forceinline__ void cp16(void* smem_dst, const void* gsrc) {
    unsigned int saddr = (unsigned int)__cvta_generic_to_shared(smem_dst);
    asm volatile("cp.async.ca.shared.global [%0], [%1], 16;"
                 :: "r"(saddr), "l"(gsrc));
}
#define CP_COMMIT() asm volatile("cp.async.commit_group;" ::: "memory")
#define CP_WAIT0()  asm volatile("cp.async.wait_group 0;" ::: "memory")

// ---------------------------------------------------------------------------
// Kernel 0: mask dtype detect + normalize
// ---------------------------------------------------------------------------
__global__ void mask_detect_kernel(const unsigned int* __restrict__ m)
{
    __shared__ int sawBig, sawFloatOne;
    if (threadIdx.x == 0) { sawBig = 0; sawFloatOne = 0; }
    __syncthreads();
    for (int i = threadIdx.x; i < 16384; i += blockDim.x) {
        unsigned int w = m[i];
        if (w == 0x3F800000u) atomicOr(&sawFloatOne, 1);
        else if (w > 1u) atomicOr(&sawBig, 1);
    }
    __syncthreads();
    if (threadIdx.x == 0)
        g_mask_mode = sawFloatOne ? 2 : (sawBig ? 0 : 1);
}

__global__ __launch_bounds__(256) void mask_convert_kernel(const void* __restrict__ m)
{
    const size_t i = (size_t)blockIdx.x * blockDim.x + threadIdx.x;
    if (i >= MASK_ELEMS) return;
    const int mode = g_mask_mode;
    unsigned char v;
    if (mode == 0)      v = ((const unsigned char*)m)[i] != 0;
    else if (mode == 1) v = ((const int*)m)[i] != 0;
    else                v = ((const float*)m)[i] != 0.0f;
    g_mask8[i] = v;
}

// ---------------------------------------------------------------------------
// Kernel 0c: convert X -> half, weights -> k-interleaved half2
// ---------------------------------------------------------------------------
__global__ __launch_bounds__(256) void preround_kernel(
    const float* __restrict__ x, const float* __restrict__ wqkv,
    const float* __restrict__ wout)
{
    const size_t j = (size_t)blockIdx.x * blockDim.x + threadIdx.x;
    const size_t i = j * 4;
    if (i < (size_t)M_ROWS * DMODEL) {
        float4 v = *(const float4*)&x[i];
        ((__half2*)g_xh)[i / 2]     = __floats2half2_rn(v.x, v.y);
        ((__half2*)g_xh)[i / 2 + 1] = __floats2half2_rn(v.z, v.w);
    }
    if (j < (size_t)(DMODEL / 2) * (THREE_D / 4)) {       // 98304
        const int kk = (int)(j / (THREE_D / 4));
        const int n4 = (int)(j % (THREE_D / 4)) * 4;
        float4 w0 = *(const float4*)&wqkv[(size_t)(2 * kk) * THREE_D + n4];
        float4 w1 = *(const float4*)&wqkv[(size_t)(2 * kk + 1) * THREE_D + n4];
        __half2* dst = &g_wqkv2[(size_t)kk * THREE_D + n4];
        dst[0] = __floats2half2_rn(w0.x, w1.x);
        dst[1] = __floats2half2_rn(w0.y, w1.y);
        dst[2] = __floats2half2_rn(w0.z, w1.z);
        dst[3] = __floats2half2_rn(w0.w, w1.w);
    }
    if (j < (size_t)(DMODEL / 2) * (DMODEL / 4)) {        // 32768
        const int kk = (int)(j / (DMODEL / 4));
        const int n4 = (int)(j % (DMODEL / 4)) * 4;
        float4 w0 = *(const float4*)&wout[(size_t)(2 * kk) * DMODEL + n4];
        float4 w1 = *(const float4*)&wout[(size_t)(2 * kk + 1) * DMODEL + n4];
        __half2* dst = &g_wout2[(size_t)kk * DMODEL + n4];
        dst[0] = __floats2half2_rn(w0.x, w1.x);
        dst[1] = __floats2half2_rn(w0.y, w1.y);
        dst[2] = __floats2half2_rn(w0.z, w1.z);
        dst[3] = __floats2half2_rn(w0.w, w1.w);
    }
}

// ---------------------------------------------------------------------------
// FP16 MMA GEMM core: 128x128 block, BK=16 (one mma-k16 per stage), 8 warps
// 4m x 2n, each m32 x n64. cp.async double-buffered.
// As[128][24]h (48B rows): frag banks 12g+t distinct.
// Bs[8][132]h2 (528B rows): frag banks 4t+g distinct.
// ---------------------------------------------------------------------------
#define GEMM_BODY3(AEXPR, BEXPR, LDA, LDBN, KDIM)                              \
    const __half* __restrict__ A = (AEXPR);                                    \
    const __half2* __restrict__ B2 = (BEXPR);                                  \
    __shared__ __half As[2][128][24];                                          \
    __shared__ __half2 Bs[2][8][132];                                          \
    const int tid = threadIdx.x;                                               \
    const int w = tid >> 5, lane = tid & 31;                                   \
    const int g = lane >> 2, t = lane & 3;                                     \
    const int n0 = blockIdx.x << 7, m0 = blockIdx.y << 7;                      \
    const int wm = (w & 3) << 5, wn = (w >> 2) << 6;                           \
    const int arow = tid >> 1, ac8 = (tid & 1) << 3;                           \
    const int brow = tid >> 5, bc4 = (tid & 31) << 2;                          \
    float acc[2][8][4] = {};                                                   \
    cp16(&As[0][arow][ac8], &A[(size_t)(m0 + arow) * LDA + ac8]);              \
    cp16(&Bs[0][brow][bc4], &B2[(size_t)brow * LDBN + n0 + bc4]);              \
    CP_COMMIT();                                                               \
    const int NS = (KDIM) / 16;                                                \
    for (int s = 0; s < NS; s++) {                                             \
        const int cur = s & 1;                                                 \
        CP_WAIT0();                                                            \
        __syncthreads();                                                       \
        if (s + 1 < NS) {                                                      \
            const int nxt = cur ^ 1;                                           \
            const int k0 = (s + 1) << 4;                                       \
            cp16(&As[nxt][arow][ac8],                                          \
                 &A[(size_t)(m0 + arow) * LDA + k0 + ac8]);                    \
            cp16(&Bs[nxt][brow][bc4],                                          \
                 &B2[(size_t)((k0 >> 1) + brow) * LDBN + n0 + bc4]);           \
            CP_COMMIT();                                                       \
        }                                                                      \
        unsigned int a0[4], a1[4];                                             \
        a0[0] = *(const unsigned int*)&As[cur][wm + g][2 * t];                 \
        a0[1] = *(const unsigned int*)&As[cur][wm + g + 8][2 * t];             \
        a0[2] = *(const unsigned int*)&As[cur][wm + g][2 * t + 8];             \
        a0[3] = *(const unsigned int*)&As[cur][wm + g + 8][2 * t + 8];         \
        a1[0] = *(const unsigned int*)&As[cur][wm + 16 + g][2 * t];            \
        a1[1] = *(const unsigned int*)&As[cur][wm + 24 + g][2 * t];            \
        a1[2] = *(const unsigned int*)&As[cur][wm + 16 + g][2 * t + 8];        \
        a1[3] = *(const unsigned int*)&As[cur][wm + 24 + g][2 * t + 8];        \
        _Pragma("unroll")                                                      \
        for (int nt = 0; nt < 8; nt++) {                                       \
            unsigned int b0 = *(const unsigned int*)&Bs[cur][t][wn + nt * 8 + g]; \
            unsigned int b1 = *(const unsigned int*)&Bs[cur][t + 4][wn + nt * 8 + g]; \
            mma_f16(acc[0][nt], a0, b0, b1);                                   \
            mma_f16(acc[1][nt], a1, b0, b1);                                   \
        }                                                                      \
    }

// ---------------------------------------------------------------------------
// Kernel 1: QKV projection; epilogue converts to fp16, scatters Q/K row-major
// and V transposed.
// ---------------------------------------------------------------------------
__global__ __launch_bounds__(256, 2) void qkv_mma_kernel()
{
    GEMM_BODY3((const __half*)g_xh, (const __half2*)g_wqkv2, DMODEL, THREE_D, DMODEL)

#pragma unroll
    for (int nt = 0; nt < 8; nt++) {
        const int c = n0 + wn + nt * 8 + 2 * t;
        const int which = c >> 9;
        const int dd = c & 511;
        const int h = dd >> 6;
        const int dk = dd & 63;
#pragma unroll
        for (int mh = 0; mh < 2; mh++) {
#pragma unroll
            for (int half = 0; half < 2; half++) {
                const int m = m0 + wm + mh * 16 + g + half * 8;
                const int b = m >> 11;
                const int n = m & (NSEQ - 1);
                const float v0 = acc[mh][nt][half * 2];
                const float v1 = acc[mh][nt][half * 2 + 1];
                if (which == 0) {
                    *(__half2*)&g_q[(((size_t)b * NHEAD + h) * NSEQ + n) * DK + dk] =
                        __floats2half2_rn(v0, v1);
                } else if (which == 1) {
                    *(__half2*)&g_k[(((size_t)b * NHEAD + h) * NSEQ + n) * DK + dk] =
                        __floats2half2_rn(v0, v1);
                } else {
                    __half* vt = &g_vt[(((size_t)b * NHEAD + h) * DK + dk) * NSEQ + n];
                    vt[0] = __float2half_rn(v0);
                    vt[NSEQ] = __float2half_rn(v1);
                }
            }
        }
    }
}

// ---------------------------------------------------------------------------
// Kernel 2: flash attention, fp16 mma. Q direct from global to registers.
// cp.async double-buffered K/Vt/mask; P fragments packed straight from Sa
// accumulators (f16 A-layout == accumulator layout) — no shuffles, no smem P.
// smem bytes: Kb 2x9216 | Vtb 2x9216 | Mb 2x8192 = 53248
// ---------------------------------------------------------------------------
__global__ __launch_bounds__(256, 2) void attn_mma_kernel()
{
    extern __shared__ char smc[];

    const int tid  = threadIdx.x;
    const int w    = tid >> 5;
    const int lane = tid & 31;
    const int g    = lane >> 2;
    const int t    = lane & 3;
    const int qrow0 = blockIdx.x << 7;
    const int bh = blockIdx.y;
    const int b = bh >> 3, h = bh & 7;

    const __half* Kg = g_k + (size_t)bh * NSEQ * DK;
    const __half* Vtg = g_vt + (size_t)bh * DK * NSEQ;
    const unsigned char* Mgb = g_mask8 + ((size_t)b * NSEQ + qrow0) * NSEQ;

    // ---- prefetch tile 0 ----
    {
        char* Kb = smc;
        char* Vb = smc + 18432;
        char* Mb = smc + 36864;
#pragma unroll
        for (int j = 0; j < 2; j++) {
            const int e = tid + j * 256;
            const int row = e >> 3, ch = (e & 7) << 3;     // halves
            cp16(Kb + row * 144 + ch * 2, &Kg[(size_t)row * DK + ch]);
            cp16(Vb + row * 144 + ch * 2, &Vtg[(size_t)row * NSEQ + ch]);
        }
#pragma unroll
        for (int j = 0; j < 2; j++) {
            const int e = tid + j * 256;
            const int row = e >> 2, q = e & 3;
            cp16(Mb + row * 64 + q * 16, Mgb + (size_t)row * NSEQ + q * 16);
        }
        CP_COMMIT();
    }

    // ---- Q fragments straight from global (overlaps with prefetch) ----
    const int r0 = w * 16 + g;
    const size_t qrow = (size_t)bh * NSEQ + qrow0 + r0;
    unsigned int qf[4][4];
#pragma unroll
    for (int kc = 0; kc < 4; kc++) {
        qf[kc][0] = *(const unsigned int*)&g_q[qrow * DK + kc * 16 + 2 * t];
        qf[kc][1] = *(const unsigned int*)&g_q[(qrow + 8) * DK + kc * 16 + 2 * t];
        qf[kc][2] = *(const unsigned int*)&g_q[qrow * DK + kc * 16 + 2 * t + 8];
        qf[kc][3] = *(const unsigned int*)&g_q[(qrow + 8) * DK + kc * 16 + 2 * t + 8];
    }

    float Oa[8][4] = {};
    float mrow[2] = {-1e30f, -1e30f};
    float lrow[2] = {0.f, 0.f};

    for (int kti = 0; kti < NSEQ / 64; kti++) {
        const int cur = kti & 1;
        CP_WAIT0();
        __syncthreads();

        if (kti + 1 < NSEQ / 64) {
            const int nxt = cur ^ 1;
            const int kc0 = (kti + 1) << 6;
            char* Kb = smc + nxt * 9216;
            char* Vb = smc + 18432 + nxt * 9216;
            char* Mb = smc + 36864 + nxt * 8192;
#pragma unroll
            for (int j = 0; j < 2; j++) {
                const int e = tid + j * 256;
                const int row = e >> 3, ch = (e & 7) << 3;
                cp16(Kb + row * 144 + ch * 2, &Kg[(size_t)(kc0 + row) * DK + ch]);
                cp16(Vb + row * 144 + ch * 2, &Vtg[(size_t)row * NSEQ + kc0 + ch]);
            }
#pragma unroll
            for (int j = 0; j < 2; j++) {
                const int e = tid + j * 256;
                const int row = e >> 2, q = e & 3;
                cp16(Mb + row * 64 + q * 16,
                     Mgb + (size_t)row * NSEQ + kc0 + q * 16);
            }
            CP_COMMIT();
        }

        const __half* Ks  = (const __half*)(smc + cur * 9216);
        const __half* Vts = (const __half*)(smc + 18432 + cur * 9216);
        const unsigned char* Ms = (const unsigned char*)(smc + 36864 + cur * 8192);

        // ---- S = Q @ K^T ----
        float Sa[8][4] = {};
#pragma unroll
        for (int kc = 0; kc < 4; kc++) {
#pragma unroll
            for (int nt = 0; nt < 8; nt++) {
                const __half* kr = &Ks[(nt * 8 + g) * 72 + kc * 16 + 2 * t];
                mma_f16(Sa[nt], qf[kc],
                        *(const unsigned int*)kr,
                        *(const unsigned int*)(kr + 8));
            }
        }

        // ---- mask + online softmax ----
        unsigned int mbits = 0;
        float rmax0 = -1e30f, rmax1 = -1e30f;
#pragma unroll
        for (int nt = 0; nt < 8; nt++) {
            const int c = nt * 8 + 2 * t;
            uchar2 m0 = *(const uchar2*)&Ms[r0 * 64 + c];
            uchar2 m1 = *(const uchar2*)&Ms[(r0 + 8) * 64 + c];
            Sa[nt][0] = m0.x ? Sa[nt][0] * 0.125f : -1e30f;
            Sa[nt][1] = m0.y ? Sa[nt][1] * 0.125f : -1e30f;
            Sa[nt][2] = m1.x ? Sa[nt][2] * 0.125f : -1e30f;
            Sa[nt][3] = m1.y ? Sa[nt][3] * 0.125f : -1e30f;
            mbits |= (m0.x ? 1u : 0u) << (nt * 4 + 0);
            mbits |= (m0.y ? 1u : 0u) << (nt * 4 + 1);
            mbits |= (m1.x ? 1u : 0u) << (nt * 4 + 2);
            mbits |= (m1.y ? 1u : 0u) << (nt * 4 + 3);
            rmax0 = fmaxf(rmax0, fmaxf(Sa[nt][0], Sa[nt][1]));
            rmax1 = fmaxf(rmax1, fmaxf(Sa[nt][2], Sa[nt][3]));
        }
        rmax0 = fmaxf(rmax0, __shfl_xor_sync(0xffffffffu, rmax0, 1));
        rmax0 = fmaxf(rmax0, __shfl_xor_sync(0xffffffffu, rmax0, 2));
        rmax1 = fmaxf(rmax1, __shfl_xor_sync(0xffffffffu, rmax1, 1));
        rmax1 = fmaxf(rmax1, __shfl_xor_sync(0xffffffffu, rmax1, 2));

        const float mnew0 = fmaxf(mrow[0], rmax0);
        const float mnew1 = fmaxf(mrow[1], rmax1);
        const float alpha0 = __expf(mrow[0] - mnew0);
        const float alpha1 = __expf(mrow[1] - mnew1);
        mrow[0] = mnew0; mrow[1] = mnew1;

        float rsum0 = 0.f, rsum1 = 0.f;
#pragma unroll
        for (int nt = 0; nt < 8; nt++) {
            const float p0 = ((mbits >> (nt * 4 + 0)) & 1u) ? __expf(Sa[nt][0] - mnew0) : 0.f;
            const float p1 = ((mbits >> (nt * 4 + 1)) & 1u) ? __expf(Sa[nt][1] - mnew0) : 0.f;
            const float p2 = ((mbits >> (nt * 4 + 2)) & 1u) ? __expf(Sa[nt][2] - mnew1) : 0.f;
            const float p3 = ((mbits >> (nt * 4 + 3)) & 1u) ? __expf(Sa[nt][3] - mnew1) : 0.f;
            rsum0 += p0 + p1; rsum1 += p2 + p3;
            Sa[nt][0] = p0; Sa[nt][1] = p1; Sa[nt][2] = p2; Sa[nt][3] = p3;
            Oa[nt][0] *= alpha0; Oa[nt][1] *= alpha0;
            Oa[nt][2] *= alpha1; Oa[nt][3] *= alpha1;
        }
        rsum0 += __shfl_xor_sync(0xffffffffu, rsum0, 1);
        rsum0 += __shfl_xor_sync(0xffffffffu, rsum0, 2);
        rsum1 += __shfl_xor_sync(0xffffffffu, rsum1, 1);
        rsum1 += __shfl_xor_sync(0xffffffffu, rsum1, 2);
        lrow[0] = lrow[0] * alpha0 + rsum0;
        lrow[1] = lrow[1] * alpha1 + rsum1;

        // ---- O += P @ V : A packed directly from Sa (f16 frag == acc layout)
#pragma unroll
        for (int kc = 0; kc < 4; kc++) {
            unsigned int a[4];
            a[0] = packh2(Sa[2 * kc][0], Sa[2 * kc][1]);
            a[1] = packh2(Sa[2 * kc][2], Sa[2 * kc][3]);
            a[2] = packh2(Sa[2 * kc + 1][0], Sa[2 * kc + 1][1]);
            a[3] = packh2(Sa[2 * kc + 1][2], Sa[2 * kc + 1][3]);
#pragma unroll
            for (int nt = 0; nt < 8; nt++) {
                const __half* vr = &Vts[(nt * 8 + g) * 72 + kc * 16 + 2 * t];
                mma_f16(Oa[nt], a,
                        *(const unsigned int*)vr,
                        *(const unsigned int*)(vr + 8));
            }
        }
    }

    // ---- epilogue: normalize, convert to half, store [B][N][D] ----
    const float inv0 = 1.f / lrow[0];
    const float inv1 = 1.f / lrow[1];
    const int grow = qrow0 + r0;
#pragma unroll
    for (int nt = 0; nt < 8; nt++) {
        const int c = h * 64 + nt * 8 + 2 * t;
        *(__half2*)&g_att[((size_t)b * NSEQ + grow) * DMODEL + c] =
            __floats2half2_rn(Oa[nt][0] * inv0, Oa[nt][1] * inv0);
        *(__half2*)&g_att[((size_t)b * NSEQ + grow + 8) * DMODEL + c] =
            __floats2half2_rn(Oa[nt][2] * inv1, Oa[nt][3] * inv1);
    }
}

// ---------------------------------------------------------------------------
// Kernel 3: output projection + bias + LeakyReLU.
// ---------------------------------------------------------------------------
__global__ __launch_bounds__(256, 2) void out_mma_kernel(
    const float* __restrict__ bias, float* __restrict__ out)
{
    GEMM_BODY3((const __half*)g_att, (const __half2*)g_wout2, DMODEL, DMODEL, DMODEL)

#pragma unroll
    for (int nt = 0; nt < 8; nt++) {
        const int c = n0 + wn + nt * 8 + 2 * t;
        const float b0 = bias[c], b1 = bias[c + 1];
#pragma unroll
        for (int mh = 0; mh < 2; mh++) {
#pragma unroll
            for (int half = 0; half < 2; half++) {
                const int m = m0 + wm + mh * 16 + g + half * 8;
                float v0 = acc[mh][nt][half * 2] + b0;
                float v1 = acc[mh][nt][half * 2 + 1] + b1;
                v0 = (v0 >= 0.f) ? v0 : 0.1f * v0;
                v1 = (v1 >= 0.f) ? v1 : 0.1f * v1;
                *(float2*)&out[(size_t)m * DMODEL + c] = make_float2(v0, v1);
            }
        }
    }
}

// ---------------------------------------------------------------------------
extern "C" void kernel_launch(void* const* d_in, const int* in_sizes, int n_in,
                              void* d_out, int out_size)
{
    const float* x = nullptr;
    const void* mask = nullptr;
    const float* Wqkv = nullptr;
    const float* Wout = nullptr;
    const float* bout = nullptr;
    for (int i = 0; i < n_in; i++) {
        switch (in_sizes[i]) {
            case 4194304:  x    = (const float*)d_in[i]; break;
            case 16777216: mask = d_in[i];               break;
            case 786432:   Wqkv = (const float*)d_in[i]; break;
            case 262144:   Wout = (const float*)d_in[i]; break;
            case 512:      bout = (const float*)d_in[i]; break;
        }
    }
    float* out = (float*)d_out;

    cudaFuncSetAttribute(attn_mma_kernel,
                         cudaFuncAttributeMaxDynamicSharedMemorySize, 53248);

    mask_detect_kernel<<<1, 256>>>((const unsigned int*)mask);
    mask_convert_kernel<<<(unsigned)((MASK_ELEMS + 255) / 256), 256>>>(mask);
    preround_kernel<<<4096, 256>>>(x, Wqkv, Wout);
    qkv_mma_kernel<<<dim3(THREE_D / 128, M_ROWS / 128), 256>>>();
    attn_mma_kernel<<<dim3(NSEQ / 128, BH), 256, 53248>>>();
    out_mma_kernel<<<dim3(DMODEL / 128, M_ROWS / 128), 256>>>(bout, out);
}

// round 16
// speedup vs baseline: 5.0370x; 1.0826x over previous
#include <cuda_runtime.h>
#include <cuda_fp16.h>
#include <cstdint>

#define BSZ 4
#define NSEQ 2048
#define DMODEL 512
#define NHEAD 8
#define DK 64
#define BH (BSZ * NHEAD)          // 32
#define M_ROWS (BSZ * NSEQ)       // 8192
#define THREE_D (3 * DMODEL)      // 1536
#define MASK_ELEMS ((size_t)BSZ * NSEQ * NSEQ)   // 16,777,216

// Scratch
__device__ __half g_q[(size_t)BH * NSEQ * DK];
__device__ __half g_k[(size_t)BH * NSEQ * DK];
__device__ __half g_vt[(size_t)BH * DK * NSEQ];          // transposed [bh][dk][key]
__device__ __half g_att[(size_t)M_ROWS * DMODEL];
__device__ __half g_xh[(size_t)M_ROWS * DMODEL];
__device__ __half2 g_wqkv2[(size_t)(DMODEL / 2) * THREE_D];
__device__ __half2 g_wout2[(size_t)(DMODEL / 2) * DMODEL];
__device__ unsigned int g_maskw[MASK_ELEMS / 32];        // 2 MB bitmask
__device__ int g_mask_mode;

// ---------------------------------------------------------------------------
// helpers
// ---------------------------------------------------------------------------
__device__ __forceinline__ void mma_f16(float* c, const unsigned int* a,
                                        unsigned int b0, unsigned int b1) {
    asm volatile(
        "mma.sync.aligned.m16n8k16.row.col.f32.f16.f16.f32 "
        "{%0,%1,%2,%3}, {%4,%5,%6,%7}, {%8,%9}, {%0,%1,%2,%3};"
        : "+f"(c[0]), "+f"(c[1]), "+f"(c[2]), "+f"(c[3])
        : "r"(a[0]), "r"(a[1]), "r"(a[2]), "r"(a[3]), "r"(b0), "r"(b1));
}

__device__ __forceinline__ unsigned int packh2(float lo, float hi) {
    __half2 h = __floats2half2_rn(lo, hi);
    return *(unsigned int*)&h;
}

__device__ __forceinline__ void cp16(void* smem_dst, const void* gsrc) {
    unsigned int saddr = (unsigned int)__cvta_generic_to_shared(smem_dst);
    asm volatile("cp.async.ca.shared.global [%0], [%1], 16;"
                 :: "r"(saddr), "l"(gsrc));
}
#define CP_COMMIT() asm volatile("cp.async.commit_group;" ::: "memory")
#define CP_WAIT0()  asm volatile("cp.async.wait_group 0;" ::: "memory")

// ---------------------------------------------------------------------------
// Kernel 0a: mask dtype detect
// ---------------------------------------------------------------------------
__global__ void mask_detect_kernel(const unsigned int* __restrict__ m)
{
    __shared__ int sawBig, sawFloatOne;
    if (threadIdx.x == 0) { sawBig = 0; sawFloatOne = 0; }
    __syncthreads();
    for (int i = threadIdx.x; i < 16384; i += blockDim.x) {
        unsigned int w = m[i];
        if (w == 0x3F800000u) atomicOr(&sawFloatOne, 1);
        else if (w > 1u) atomicOr(&sawBig, 1);
    }
    __syncthreads();
    if (threadIdx.x == 0)
        g_mask_mode = sawFloatOne ? 2 : (sawBig ? 0 : 1);
}

// Kernel 0b: pack mask to 1 bit/element via ballot
__global__ __launch_bounds__(256) void mask_pack_kernel(const void* __restrict__ m)
{
    const size_t i = (size_t)blockIdx.x * 256 + threadIdx.x;   // grid covers exactly
    const int mode = g_mask_mode;
    bool v;
    if (mode == 0)      v = ((const unsigned char*)m)[i] != 0;
    else if (mode == 1) v = ((const int*)m)[i] != 0;
    else                v = ((const float*)m)[i] != 0.0f;
    const unsigned int bal = __ballot_sync(0xffffffffu, v);
    if ((threadIdx.x & 31) == 0) g_maskw[i >> 5] = bal;
}

// ---------------------------------------------------------------------------
// Kernel 0c: X -> half, weights -> k-interleaved half2
// ---------------------------------------------------------------------------
__global__ __launch_bounds__(256) void preround_kernel(
    const float* __restrict__ x, const float* __restrict__ wqkv,
    const float* __restrict__ wout)
{
    const size_t j = (size_t)blockIdx.x * blockDim.x + threadIdx.x;
    const size_t i = j * 4;
    if (i < (size_t)M_ROWS * DMODEL) {
        float4 v = *(const float4*)&x[i];
        ((__half2*)g_xh)[i / 2]     = __floats2half2_rn(v.x, v.y);
        ((__half2*)g_xh)[i / 2 + 1] = __floats2half2_rn(v.z, v.w);
    }
    if (j < (size_t)(DMODEL / 2) * (THREE_D / 4)) {
        const int kk = (int)(j / (THREE_D / 4));
        const int n4 = (int)(j % (THREE_D / 4)) * 4;
        float4 w0 = *(const float4*)&wqkv[(size_t)(2 * kk) * THREE_D + n4];
        float4 w1 = *(const float4*)&wqkv[(size_t)(2 * kk + 1) * THREE_D + n4];
        __half2* dst = &g_wqkv2[(size_t)kk * THREE_D + n4];
        dst[0] = __floats2half2_rn(w0.x, w1.x);
        dst[1] = __floats2half2_rn(w0.y, w1.y);
        dst[2] = __floats2half2_rn(w0.z, w1.z);
        dst[3] = __floats2half2_rn(w0.w, w1.w);
    }
    if (j < (size_t)(DMODEL / 2) * (DMODEL / 4)) {
        const int kk = (int)(j / (DMODEL / 4));
        const int n4 = (int)(j % (DMODEL / 4)) * 4;
        float4 w0 = *(const float4*)&wout[(size_t)(2 * kk) * DMODEL + n4];
        float4 w1 = *(const float4*)&wout[(size_t)(2 * kk + 1) * DMODEL + n4];
        __half2* dst = &g_wout2[(size_t)kk * DMODEL + n4];
        dst[0] = __floats2half2_rn(w0.x, w1.x);
        dst[1] = __floats2half2_rn(w0.y, w1.y);
        dst[2] = __floats2half2_rn(w0.z, w1.z);
        dst[3] = __floats2half2_rn(w0.w, w1.w);
    }
}

// ---------------------------------------------------------------------------
// FP16 MMA GEMM core: 128x128 block, BK=16, 8 warps 4m x 2n, each m32 x n64.
// As[128][24]h: frag banks 12g+t -> all distinct.
// Bs[8][136]h2 (544B rows): frag banks 8t+g -> all distinct (132 was 2-way!).
// ---------------------------------------------------------------------------
#define GEMM_BODY3(AEXPR, BEXPR, LDA, LDBN, KDIM)                              \
    const __half* __restrict__ A = (AEXPR);                                    \
    const __half2* __restrict__ B2 = (BEXPR);                                  \
    __shared__ __half As[2][128][24];                                          \
    __shared__ __half2 Bs[2][8][136];                                          \
    const int tid = threadIdx.x;                                               \
    const int w = tid >> 5, lane = tid & 31;                                   \
    const int g = lane >> 2, t = lane & 3;                                     \
    const int n0 = blockIdx.x << 7, m0 = blockIdx.y << 7;                      \
    const int wm = (w & 3) << 5, wn = (w >> 2) << 6;                           \
    const int arow = tid >> 1, ac8 = (tid & 1) << 3;                           \
    const int brow = tid >> 5, bc4 = (tid & 31) << 2;                          \
    float acc[2][8][4] = {};                                                   \
    cp16(&As[0][arow][ac8], &A[(size_t)(m0 + arow) * LDA + ac8]);              \
    cp16(&Bs[0][brow][bc4], &B2[(size_t)brow * LDBN + n0 + bc4]);              \
    CP_COMMIT();                                                               \
    const int NS = (KDIM) / 16;                                                \
    for (int s = 0; s < NS; s++) {                                             \
        const int cur = s & 1;                                                 \
        CP_WAIT0();                                                            \
        __syncthreads();                                                       \
        if (s + 1 < NS) {                                                      \
            const int nxt = cur ^ 1;                                           \
            const int k0 = (s + 1) << 4;                                       \
            cp16(&As[nxt][arow][ac8],                                          \
                 &A[(size_t)(m0 + arow) * LDA + k0 + ac8]);                    \
            cp16(&Bs[nxt][brow][bc4],                                          \
                 &B2[(size_t)((k0 >> 1) + brow) * LDBN + n0 + bc4]);           \
            CP_COMMIT();                                                       \
        }                                                                      \
        unsigned int a0[4], a1[4];                                             \
        a0[0] = *(const unsigned int*)&As[cur][wm + g][2 * t];                 \
        a0[1] = *(const unsigned int*)&As[cur][wm + g + 8][2 * t];             \
        a0[2] = *(const unsigned int*)&As[cur][wm + g][2 * t + 8];             \
        a0[3] = *(const unsigned int*)&As[cur][wm + g + 8][2 * t + 8];         \
        a1[0] = *(const unsigned int*)&As[cur][wm + 16 + g][2 * t];            \
        a1[1] = *(const unsigned int*)&As[cur][wm + 24 + g][2 * t];            \
        a1[2] = *(const unsigned int*)&As[cur][wm + 16 + g][2 * t + 8];        \
        a1[3] = *(const unsigned int*)&As[cur][wm + 24 + g][2 * t + 8];        \
        _Pragma("unroll")                                                      \
        for (int nt = 0; nt < 8; nt++) {                                       \
            unsigned int b0 = *(const unsigned int*)&Bs[cur][t][wn + nt * 8 + g]; \
            unsigned int b1 = *(const unsigned int*)&Bs[cur][t + 4][wn + nt * 8 + g]; \
            mma_f16(acc[0][nt], a0, b0, b1);                                   \
            mma_f16(acc[1][nt], a1, b0, b1);                                   \
        }                                                                      \
    }

// ---------------------------------------------------------------------------
// Kernel 1: QKV projection; scatter Q/K row-major, V transposed.
// ---------------------------------------------------------------------------
__global__ __launch_bounds__(256, 2) void qkv_mma_kernel()
{
    GEMM_BODY3((const __half*)g_xh, (const __half2*)g_wqkv2, DMODEL, THREE_D, DMODEL)

#pragma unroll
    for (int nt = 0; nt < 8; nt++) {
        const int c = n0 + wn + nt * 8 + 2 * t;
        const int which = c >> 9;
        const int dd = c & 511;
        const int h = dd >> 6;
        const int dk = dd & 63;
#pragma unroll
        for (int mh = 0; mh < 2; mh++) {
#pragma unroll
            for (int half = 0; half < 2; half++) {
                const int m = m0 + wm + mh * 16 + g + half * 8;
                const int b = m >> 11;
                const int n = m & (NSEQ - 1);
                const float v0 = acc[mh][nt][half * 2];
                const float v1 = acc[mh][nt][half * 2 + 1];
                if (which == 0) {
                    *(__half2*)&g_q[(((size_t)b * NHEAD + h) * NSEQ + n) * DK + dk] =
                        __floats2half2_rn(v0, v1);
                } else if (which == 1) {
                    *(__half2*)&g_k[(((size_t)b * NHEAD + h) * NSEQ + n) * DK + dk] =
                        __floats2half2_rn(v0, v1);
                } else {
                    __half* vt = &g_vt[(((size_t)b * NHEAD + h) * DK + dk) * NSEQ + n];
                    vt[0] = __float2half_rn(v0);
                    vt[NSEQ] = __float2half_rn(v1);
                }
            }
        }
    }
}

// ---------------------------------------------------------------------------
// Kernel 2: flash attention, fp16 mma. Mask read as bit-words from global
// (no staging). cp.async double-buffered K/Vt only.
// smem: Kb 2x9216 | Vtb 2x9216 = 36864 B
// ---------------------------------------------------------------------------
__global__ __launch_bounds__(256, 2) void attn_mma_kernel()
{
    extern __shared__ char smc[];

    const int tid  = threadIdx.x;
    const int w    = tid >> 5;
    const int lane = tid & 31;
    const int g    = lane >> 2;
    const int t    = lane & 3;
    const int qrow0 = blockIdx.x << 7;
    const int bh = blockIdx.y;
    const int b = bh >> 3, h = bh & 7;

    const __half* Kg = g_k + (size_t)bh * NSEQ * DK;
    const __half* Vtg = g_vt + (size_t)bh * DK * NSEQ;

    // ---- prefetch tile 0 ----
    {
        char* Kb = smc;
        char* Vb = smc + 18432;
#pragma unroll
        for (int j = 0; j < 2; j++) {
            const int e = tid + j * 256;
            const int row = e >> 3, ch = (e & 7) << 3;
            cp16(Kb + row * 144 + ch * 2, &Kg[(size_t)row * DK + ch]);
            cp16(Vb + row * 144 + ch * 2, &Vtg[(size_t)row * NSEQ + ch]);
        }
        CP_COMMIT();
    }

    // ---- Q fragments straight from global ----
    const int r0 = w * 16 + g;
    const size_t qrow = (size_t)bh * NSEQ + qrow0 + r0;
    unsigned int qf[4][4];
#pragma unroll
    for (int kc = 0; kc < 4; kc++) {
        qf[kc][0] = *(const unsigned int*)&g_q[qrow * DK + kc * 16 + 2 * t];
        qf[kc][1] = *(const unsigned int*)&g_q[(qrow + 8) * DK + kc * 16 + 2 * t];
        qf[kc][2] = *(const unsigned int*)&g_q[qrow * DK + kc * 16 + 2 * t + 8];
        qf[kc][3] = *(const unsigned int*)&g_q[(qrow + 8) * DK + kc * 16 + 2 * t + 8];
    }

    float Oa[8][4] = {};
    float mrow[2] = {-1e30f, -1e30f};
    float lrow[2] = {0.f, 0.f};

    // mask bit-word bases: 64 words per mask row
    const unsigned int* Mw0 = g_maskw + ((size_t)b * NSEQ + qrow0 + r0) * 64;
    const unsigned int* Mw1 = Mw0 + 8 * 64;

    for (int kti = 0; kti < NSEQ / 64; kti++) {
        const int cur = kti & 1;

        // load this tile's mask bits early (independent of smem wait)
        const uint2 mw0 = *(const uint2*)&Mw0[kti * 2];
        const uint2 mw1 = *(const uint2*)&Mw1[kti * 2];

        CP_WAIT0();
        __syncthreads();

        if (kti + 1 < NSEQ / 64) {
            const int nxt = cur ^ 1;
            const int kc0 = (kti + 1) << 6;
            char* Kb = smc + nxt * 9216;
            char* Vb = smc + 18432 + nxt * 9216;
#pragma unroll
            for (int j = 0; j < 2; j++) {
                const int e = tid + j * 256;
                const int row = e >> 3, ch = (e & 7) << 3;
                cp16(Kb + row * 144 + ch * 2, &Kg[(size_t)(kc0 + row) * DK + ch]);
                cp16(Vb + row * 144 + ch * 2, &Vtg[(size_t)row * NSEQ + kc0 + ch]);
            }
            CP_COMMIT();
        }

        const __half* Ks  = (const __half*)(smc + cur * 9216);
        const __half* Vts = (const __half*)(smc + 18432 + cur * 9216);

        // ---- S = Q @ K^T ----
        float Sa[8][4] = {};
#pragma unroll
        for (int kc = 0; kc < 4; kc++) {
#pragma unroll
            for (int nt = 0; nt < 8; nt++) {
                const __half* kr = &Ks[(nt * 8 + g) * 72 + kc * 16 + 2 * t];
                mma_f16(Sa[nt], qf[kc],
                        *(const unsigned int*)kr,
                        *(const unsigned int*)(kr + 8));
            }
        }

        // ---- mask (from bit-words) + online softmax ----
        unsigned int mbits = 0;
        float rmax0 = -1e30f, rmax1 = -1e30f;
#pragma unroll
        for (int nt = 0; nt < 8; nt++) {
            const int sh = ((nt & 3) << 3) + 2 * t;
            const unsigned int w0 = (nt < 4 ? mw0.x : mw0.y) >> sh;
            const unsigned int w1 = (nt < 4 ? mw1.x : mw1.y) >> sh;
            const unsigned int m00 = w0 & 1u, m01 = (w0 >> 1) & 1u;
            const unsigned int m10 = w1 & 1u, m11 = (w1 >> 1) & 1u;
            Sa[nt][0] = m00 ? Sa[nt][0] * 0.125f : -1e30f;
            Sa[nt][1] = m01 ? Sa[nt][1] * 0.125f : -1e30f;
            Sa[nt][2] = m10 ? Sa[nt][2] * 0.125f : -1e30f;
            Sa[nt][3] = m11 ? Sa[nt][3] * 0.125f : -1e30f;
            mbits |= m00 << (nt * 4 + 0);
            mbits |= m01 << (nt * 4 + 1);
            mbits |= m10 << (nt * 4 + 2);
            mbits |= m11 << (nt * 4 + 3);
            rmax0 = fmaxf(rmax0, fmaxf(Sa[nt][0], Sa[nt][1]));
            rmax1 = fmaxf(rmax1, fmaxf(Sa[nt][2], Sa[nt][3]));
        }
        rmax0 = fmaxf(rmax0, __shfl_xor_sync(0xffffffffu, rmax0, 1));
        rmax0 = fmaxf(rmax0, __shfl_xor_sync(0xffffffffu, rmax0, 2));
        rmax1 = fmaxf(rmax1, __shfl_xor_sync(0xffffffffu, rmax1, 1));
        rmax1 = fmaxf(rmax1, __shfl_xor_sync(0xffffffffu, rmax1, 2));

        const float mnew0 = fmaxf(mrow[0], rmax0);
        const float mnew1 = fmaxf(mrow[1], rmax1);
        const float alpha0 = __expf(mrow[0] - mnew0);
        const float alpha1 = __expf(mrow[1] - mnew1);
        mrow[0] = mnew0; mrow[1] = mnew1;

        float rsum0 = 0.f, rsum1 = 0.f;
#pragma unroll
        for (int nt = 0; nt < 8; nt++) {
            const float p0 = ((mbits >> (nt * 4 + 0)) & 1u) ? __expf(Sa[nt][0] - mnew0) : 0.f;
            const float p1 = ((mbits >> (nt * 4 + 1)) & 1u) ? __expf(Sa[nt][1] - mnew0) : 0.f;
            const float p2 = ((mbits >> (nt * 4 + 2)) & 1u) ? __expf(Sa[nt][2] - mnew1) : 0.f;
            const float p3 = ((mbits >> (nt * 4 + 3)) & 1u) ? __expf(Sa[nt][3] - mnew1) : 0.f;
            rsum0 += p0 + p1; rsum1 += p2 + p3;
            Sa[nt][0] = p0; Sa[nt][1] = p1; Sa[nt][2] = p2; Sa[nt][3] = p3;
            Oa[nt][0] *= alpha0; Oa[nt][1] *= alpha0;
            Oa[nt][2] *= alpha1; Oa[nt][3] *= alpha1;
        }
        rsum0 += __shfl_xor_sync(0xffffffffu, rsum0, 1);
        rsum0 += __shfl_xor_sync(0xffffffffu, rsum0, 2);
        rsum1 += __shfl_xor_sync(0xffffffffu, rsum1, 1);
        rsum1 += __shfl_xor_sync(0xffffffffu, rsum1, 2);
        lrow[0] = lrow[0] * alpha0 + rsum0;
        lrow[1] = lrow[1] * alpha1 + rsum1;

        // ---- O += P @ V ----
#pragma unroll
        for (int kc = 0; kc < 4; kc++) {
            unsigned int a[4];
            a[0] = packh2(Sa[2 * kc][0], Sa[2 * kc][1]);
            a[1] = packh2(Sa[2 * kc][2], Sa[2 * kc][3]);
            a[2] = packh2(Sa[2 * kc + 1][0], Sa[2 * kc + 1][1]);
            a[3] = packh2(Sa[2 * kc + 1][2], Sa[2 * kc + 1][3]);
#pragma unroll
            for (int nt = 0; nt < 8; nt++) {
                const __half* vr = &Vts[(nt * 8 + g) * 72 + kc * 16 + 2 * t];
                mma_f16(Oa[nt], a,
                        *(const unsigned int*)vr,
                        *(const unsigned int*)(vr + 8));
            }
        }
    }

    // ---- epilogue ----
    const float inv0 = 1.f / lrow[0];
    const float inv1 = 1.f / lrow[1];
    const int grow = qrow0 + r0;
#pragma unroll
    for (int nt = 0; nt < 8; nt++) {
        const int c = h * 64 + nt * 8 + 2 * t;
        *(__half2*)&g_att[((size_t)b * NSEQ + grow) * DMODEL + c] =
            __floats2half2_rn(Oa[nt][0] * inv0, Oa[nt][1] * inv0);
        *(__half2*)&g_att[((size_t)b * NSEQ + grow + 8) * DMODEL + c] =
            __floats2half2_rn(Oa[nt][2] * inv1, Oa[nt][3] * inv1);
    }
}

// ---------------------------------------------------------------------------
// Kernel 3: output projection + bias + LeakyReLU.
// ---------------------------------------------------------------------------
__global__ __launch_bounds__(256, 2) void out_mma_kernel(
    const float* __restrict__ bias, float* __restrict__ out)
{
    GEMM_BODY3((const __half*)g_att, (const __half2*)g_wout2, DMODEL, DMODEL, DMODEL)

#pragma unroll
    for (int nt = 0; nt < 8; nt++) {
        const int c = n0 + wn + nt * 8 + 2 * t;
        const float b0 = bias[c], b1 = bias[c + 1];
#pragma unroll
        for (int mh = 0; mh < 2; mh++) {
#pragma unroll
            for (int half = 0; half < 2; half++) {
                const int m = m0 + wm + mh * 16 + g + half * 8;
                float v0 = acc[mh][nt][half * 2] + b0;
                float v1 = acc[mh][nt][half * 2 + 1] + b1;
                v0 = (v0 >= 0.f) ? v0 : 0.1f * v0;
                v1 = (v1 >= 0.f) ? v1 : 0.1f * v1;
                *(float2*)&out[(size_t)m * DMODEL + c] = make_float2(v0, v1);
            }
        }
    }
}

// ---------------------------------------------------------------------------
extern "C" void kernel_launch(void* const* d_in, const int* in_sizes, int n_in,
                              void* d_out, int out_size)
{
    const float* x = nullptr;
    const void* mask = nullptr;
    const float* Wqkv = nullptr;
    const float* Wout = nullptr;
    const float* bout = nullptr;
    for (int i = 0; i < n_in; i++) {
        switch (in_sizes[i]) {
            case 4194304:  x    = (const float*)d_in[i]; break;
            case 16777216: mask = d_in[i];               break;
            case 786432:   Wqkv = (const float*)d_in[i]; break;
            case 262144:   Wout = (const float*)d_in[i]; break;
            case 512:      bout = (const float*)d_in[i]; break;
        }
    }
    float* out = (float*)d_out;

    cudaFuncSetAttribute(attn_mma_kernel,
                         cudaFuncAttributeMaxDynamicSharedMemorySize, 36864);

    mask_detect_kernel<<<1, 256>>>((const unsigned int*)mask);
    mask_pack_kernel<<<(unsigned)(MASK_ELEMS / 256), 256>>>(mask);
    preround_kernel<<<4096, 256>>>(x, Wqkv, Wout);
    qkv_mma_kernel<<<dim3(THREE_D / 128, M_ROWS / 128), 256>>>();
    attn_mma_kernel<<<dim3(NSEQ / 128, BH), 256, 36864>>>();
    out_mma_kernel<<<dim3(DMODEL / 128, M_ROWS / 128), 256>>>(bout, out);
}